// round 1
// baseline (speedup 1.0000x reference)
#include <cuda_runtime.h>
#include <math.h>

// ---------------- problem constants ----------------
#define BB 32
#define TT 2048
#define CC 512          // E == F == 512
#define NN 65536        // B*T
#define HH 8
#define HD 64
#define EPS 1e-5

// ---------------- scratch (device globals; allocation-free rule) ----------
__device__ float gX[33554432];   // state, layout (C, B, T)
__device__ float gY[33554432];   // normalized copy
__device__ float gD[33554432];   // dwconv out / attention out
__device__ float gQ[33554432];
__device__ float gK[33554432];
__device__ float gV[33554432];

__device__ double g_bpart[32 * 32 * 2];      // per-batch partial (sum, sumsq)
__device__ float  g_bmean[32], g_brstd[32];
__device__ double g_tpart[2048 * 8 * 2];     // per-t partial (sum, sumsq)
__device__ float  g_tmean[2048], g_trstd[2048];

// ---------------- input transpose + positional encoding -------------------
// X[c,b,t] = in[b,t,c] + pe(b,c)   (pe indexed by BATCH — faithful quirk)
__global__ void k_transpose_in(const float* __restrict__ in, float* __restrict__ X) {
    __shared__ float tile[32][33];
    int b = blockIdx.z;
    int t0 = blockIdx.x * 32, c0 = blockIdx.y * 32;
    int tx = threadIdx.x, ty = threadIdx.y;
    #pragma unroll
    for (int i = ty; i < 32; i += 8)
        tile[i][tx] = in[((size_t)b * TT + t0 + i) * CC + c0 + tx];
    __syncthreads();
    #pragma unroll
    for (int i = ty; i < 32; i += 8) {
        int c = c0 + i;
        float div = expf((float)(c & ~1) * (-9.210340371976184f / 512.0f));
        float ang = (float)b * div;
        float pe = (c & 1) ? cosf(ang) : sinf(ang);
        X[((size_t)c * BB + b) * TT + t0 + tx] = tile[tx][i] + pe;
    }
}

// ---------------- per-batch LN stats (over C,T at fixed b) ----------------
__global__ void k_bstats(const float* __restrict__ X) {
    int b = blockIdx.x, cy = blockIdx.y;
    int tid = threadIdx.x;
    double s = 0, q = 0;
    for (int c = cy * 16; c < cy * 16 + 16; c++) {
        const float* row = X + ((size_t)c * BB + b) * TT;
        for (int t = tid; t < TT; t += 256) { float v = row[t]; s += v; q += (double)v * v; }
    }
    __shared__ double ss[256], qq[256];
    ss[tid] = s; qq[tid] = q; __syncthreads();
    for (int o = 128; o > 0; o >>= 1) {
        if (tid < o) { ss[tid] += ss[tid + o]; qq[tid] += qq[tid + o]; }
        __syncthreads();
    }
    if (tid == 0) {
        g_bpart[(b * 32 + cy) * 2] = ss[0];
        g_bpart[(b * 32 + cy) * 2 + 1] = qq[0];
    }
}

__global__ void k_bfinal() {
    int b = threadIdx.x;
    if (b < 32) {
        double s = 0, q = 0;
        for (int i = 0; i < 32; i++) { s += g_bpart[(b * 32 + i) * 2]; q += g_bpart[(b * 32 + i) * 2 + 1]; }
        double n = 1048576.0;
        double mu = s / n;
        double var = q / n - mu * mu;
        g_bmean[b] = (float)mu;
        g_brstd[b] = (float)(1.0 / sqrt(var + (double)EPS));
    }
}

// ---------------- fused per-batch-LN + depthwise conv (k=7, pad 3) --------
__global__ void k_dwconv(const float* __restrict__ X, const float* __restrict__ dww,
                         const float* __restrict__ dwb, float* __restrict__ D) {
    int c = blockIdx.x, b = blockIdx.y;
    int tid = threadIdx.x;
    __shared__ float s[TT + 8];
    float mu = g_bmean[b], r = g_brstd[b];
    const float* row = X + ((size_t)c * BB + b) * TT;
    for (int t = tid; t < TT; t += 256) s[t + 3] = (row[t] - mu) * r;
    if (tid < 3) { s[tid] = 0.0f; s[TT + 3 + tid] = 0.0f; }
    __syncthreads();
    float w0 = dww[c * 7 + 0], w1 = dww[c * 7 + 1], w2 = dww[c * 7 + 2], w3 = dww[c * 7 + 3];
    float w4 = dww[c * 7 + 4], w5 = dww[c * 7 + 5], w6 = dww[c * 7 + 6];
    float bias = dwb[c];
    float* drow = D + ((size_t)c * BB + b) * TT;
    for (int t = tid; t < TT; t += 256) {
        float acc = bias;
        acc += w0 * s[t + 0]; acc += w1 * s[t + 1]; acc += w2 * s[t + 2];
        acc += w3 * s[t + 3]; acc += w4 * s[t + 4]; acc += w5 * s[t + 5];
        acc += w6 * s[t + 6];
        drow[t] = acc;
    }
}

// ---------------- per-batch normalize (materialize Y = LN(X)) -------------
__global__ void k_normb(const float* __restrict__ X, float* __restrict__ Y) {
    size_t i = ((size_t)blockIdx.x * 256 + threadIdx.x) * 4;
    int b = (int)((i / TT) & 31);
    float mu = g_bmean[b], r = g_brstd[b];
    float4 v = *(const float4*)&X[i];
    v.x = (v.x - mu) * r; v.y = (v.y - mu) * r; v.z = (v.z - mu) * r; v.w = (v.w - mu) * r;
    *(float4*)&Y[i] = v;
}

// ---------------- SGEMM: C[M=512, N=65536] (+)= W[512,512] @ Bm + bias ----
template <int BETA>
__global__ void __launch_bounds__(256, 2)
k_sgemm(const float* __restrict__ W, const float* __restrict__ Bm,
        const float* __restrict__ bias, float* __restrict__ C) {
    const int Kd = 512, N = NN;
    __shared__ float As[16][128];
    __shared__ float Bs[16][128];
    int m0 = blockIdx.x * 128;       // 4 m-blocks (fast axis -> B tiles L2-resident)
    int n0 = blockIdx.y * 128;       // 512 n-blocks
    int tid = threadIdx.x;
    int wr = tid >> 2, wc = (tid & 3) << 2;   // W loads
    int br = tid >> 5, bc = (tid & 31) << 2;  // B loads
    int ty = tid >> 4, tx = tid & 15;
    float acc[8][8];
    #pragma unroll
    for (int i = 0; i < 8; i++)
        #pragma unroll
        for (int j = 0; j < 8; j++) acc[i][j] = 0.0f;

    for (int k0 = 0; k0 < Kd; k0 += 16) {
        float4 a0 = *(const float4*)&W[(size_t)(m0 + wr) * Kd + k0 + wc];
        float4 a1 = *(const float4*)&W[(size_t)(m0 + wr + 64) * Kd + k0 + wc];
        float4 b0 = *(const float4*)&Bm[(size_t)(k0 + br) * N + n0 + bc];
        float4 b1 = *(const float4*)&Bm[(size_t)(k0 + br + 8) * N + n0 + bc];
        __syncthreads();
        As[wc + 0][wr] = a0.x; As[wc + 1][wr] = a0.y; As[wc + 2][wr] = a0.z; As[wc + 3][wr] = a0.w;
        As[wc + 0][wr + 64] = a1.x; As[wc + 1][wr + 64] = a1.y; As[wc + 2][wr + 64] = a1.z; As[wc + 3][wr + 64] = a1.w;
        *(float4*)&Bs[br][bc] = b0;
        *(float4*)&Bs[br + 8][bc] = b1;
        __syncthreads();
        #pragma unroll
        for (int kk = 0; kk < 16; kk++) {
            float a[8], bb[8];
            *(float4*)&a[0] = *(const float4*)&As[kk][ty * 8];
            *(float4*)&a[4] = *(const float4*)&As[kk][ty * 8 + 4];
            *(float4*)&bb[0] = *(const float4*)&Bs[kk][tx * 8];
            *(float4*)&bb[4] = *(const float4*)&Bs[kk][tx * 8 + 4];
            #pragma unroll
            for (int i = 0; i < 8; i++)
                #pragma unroll
                for (int j = 0; j < 8; j++)
                    acc[i][j] += a[i] * bb[j];
        }
    }

    #pragma unroll
    for (int i = 0; i < 8; i++) {
        int m = m0 + ty * 8 + i;
        float bv = bias[m];
        size_t base = (size_t)m * N + n0 + tx * 8;
        float4 c0, c1;
        c0.x = acc[i][0] + bv; c0.y = acc[i][1] + bv; c0.z = acc[i][2] + bv; c0.w = acc[i][3] + bv;
        c1.x = acc[i][4] + bv; c1.y = acc[i][5] + bv; c1.z = acc[i][6] + bv; c1.w = acc[i][7] + bv;
        if (BETA) {
            float4 o0 = *(const float4*)&C[base];
            float4 o1 = *(const float4*)&C[base + 4];
            c0.x += o0.x; c0.y += o0.y; c0.z += o0.z; c0.w += o0.w;
            c1.x += o1.x; c1.y += o1.y; c1.z += o1.z; c1.w += o1.w;
        }
        *(float4*)&C[base] = c0;
        *(float4*)&C[base + 4] = c1;
    }
}

// ---------------- attention over the batch axis (B=32 per (t,h)) ----------
// Q/K/V layout: [(h*64+d)*32 + b]*2048 + t.  Block = 8 consecutive t, one h.
#define AT 8
#define SQ_OFF 0
#define SK_OFF 16384
#define SV_OFF 32768
#define ST_OFF 51200
#define ATTN_SMEM_FLOATS (16384 + 16384 + 18432 + 1056)
#define ATTN_SMEM_BYTES (ATTN_SMEM_FLOATS * 4)

__global__ void k_attn(const float* __restrict__ Q, const float* __restrict__ Kg,
                       const float* __restrict__ Vg, float* __restrict__ O) {
    extern __shared__ float sm[];
    float* smq = sm + SQ_OFF;   // [8][64][32], later reused for p: [8][32 x stride36]
    float* smk = sm + SK_OFF;   // [8][64][32]
    float* smv = sm + SV_OFF;   // [8][64][stride 36]
    float* st  = sm + ST_OFF;   // [32][33] one-t scores
    int h = blockIdx.y;
    int t0 = blockIdx.x * AT;
    int tid = threadIdx.x;

    // load
    for (int p0 = tid; p0 < 2048; p0 += 256) {
        int d = p0 >> 5, b = p0 & 31;
        size_t base = ((size_t)(h * 64 + d) * 32 + b) * 2048 + t0;
        float4 a0 = *(const float4*)&Q[base];  float4 a1 = *(const float4*)&Q[base + 4];
        float4 k0 = *(const float4*)&Kg[base]; float4 k1 = *(const float4*)&Kg[base + 4];
        float4 v0 = *(const float4*)&Vg[base]; float4 v1 = *(const float4*)&Vg[base + 4];
        float qa[8] = {a0.x, a0.y, a0.z, a0.w, a1.x, a1.y, a1.z, a1.w};
        float ka[8] = {k0.x, k0.y, k0.z, k0.w, k1.x, k1.y, k1.z, k1.w};
        float va[8] = {v0.x, v0.y, v0.z, v0.w, v1.x, v1.y, v1.z, v1.w};
        #pragma unroll
        for (int s = 0; s < 8; s++) {
            smq[(s * 64 + d) * 32 + b] = qa[s];
            smk[(s * 64 + d) * 32 + b] = ka[s];
            smv[(s * 64 + d) * 36 + b] = va[s];
        }
    }
    __syncthreads();

    const float scale = 0.125f;
    int sb = tid >> 3, sp0 = (tid & 7) * 4;
    for (int ttk = 0; ttk < AT; ttk++) {
        // scores: 1024 = 256 threads x 4
        float a0 = 0, a1 = 0, a2 = 0, a3 = 0;
        #pragma unroll
        for (int d = 0; d < 64; d++) {
            float qv = smq[(ttk * 64 + d) * 32 + sb];
            float4 kv = *(const float4*)&smk[(ttk * 64 + d) * 32 + sp0];
            a0 += qv * kv.x; a1 += qv * kv.y; a2 += qv * kv.z; a3 += qv * kv.w;
        }
        st[sb * 33 + sp0 + 0] = a0 * scale;
        st[sb * 33 + sp0 + 1] = a1 * scale;
        st[sb * 33 + sp0 + 2] = a2 * scale;
        st[sb * 33 + sp0 + 3] = a3 * scale;
        __syncthreads();
        // softmax rows (one thread per b-row); write p into retired smq region
        if (tid < 32) {
            const float* row = st + tid * 33;
            float mx = -1e30f;
            #pragma unroll
            for (int j = 0; j < 32; j++) mx = fmaxf(mx, row[j]);
            float ev[32]; float sum = 0.0f;
            #pragma unroll
            for (int j = 0; j < 32; j++) { ev[j] = expf(row[j] - mx); sum += ev[j]; }
            float inv = 1.0f / sum;
            #pragma unroll
            for (int j = 0; j < 32; j++) smq[ttk * 1152 + tid * 36 + j] = ev[j] * inv;
        }
        __syncthreads();
    }

    // output: out[b,d] per t' = sum_b' p[b,b'] v[b',d]
    for (int rep = 0; rep < 8; rep++) {
        int o = tid + rep * 256;
        int ob = o >> 6, od = o & 63;
        float outv[8];
        #pragma unroll
        for (int s = 0; s < 8; s++) {
            float acc = 0.0f;
            #pragma unroll
            for (int bp = 0; bp < 32; bp += 4) {
                float4 pv = *(const float4*)&smq[s * 1152 + ob * 36 + bp];
                float4 vv = *(const float4*)&smv[(s * 64 + od) * 36 + bp];
                acc += pv.x * vv.x + pv.y * vv.y + pv.z * vv.z + pv.w * vv.w;
            }
            outv[s] = acc;
        }
        size_t base = ((size_t)(h * 64 + od) * 32 + ob) * 2048 + t0;
        float4 w0 = {outv[0], outv[1], outv[2], outv[3]};
        float4 w1 = {outv[4], outv[5], outv[6], outv[7]};
        *(float4*)&O[base] = w0;
        *(float4*)&O[base + 4] = w1;
    }
}

// ---------------- per-t LN stats (over C,B at fixed t) --------------------
__global__ void k_tstats(const float* __restrict__ X) {
    int t = blockIdx.x * 32 + threadIdx.x;
    int ry = blockIdx.y;   // 8 row-chunks of 2048 rows (rows = c*32+b, 16384 total)
    double s = 0, q = 0;
    for (int r = ry * 2048 + threadIdx.y; r < (ry + 1) * 2048; r += 8) {
        float v = X[(size_t)r * TT + t];
        s += v; q += (double)v * v;
    }
    __shared__ double ss[8][32], qq[8][32];
    ss[threadIdx.y][threadIdx.x] = s;
    qq[threadIdx.y][threadIdx.x] = q;
    __syncthreads();
    if (threadIdx.y == 0) {
        double S = 0, Qq = 0;
        #pragma unroll
        for (int j = 0; j < 8; j++) { S += ss[j][threadIdx.x]; Qq += qq[j][threadIdx.x]; }
        g_tpart[(t * 8 + ry) * 2] = S;
        g_tpart[(t * 8 + ry) * 2 + 1] = Qq;
    }
}

__global__ void k_tfinal() {
    int t = blockIdx.x * 256 + threadIdx.x;
    double s = 0, q = 0;
    for (int i = 0; i < 8; i++) { s += g_tpart[(t * 8 + i) * 2]; q += g_tpart[(t * 8 + i) * 2 + 1]; }
    double n = 16384.0;
    double mu = s / n;
    double var = q / n - mu * mu;
    g_tmean[t] = (float)mu;
    g_trstd[t] = (float)(1.0 / sqrt(var + (double)EPS));
}

__global__ void k_normt(const float* __restrict__ X, float* __restrict__ Y) {
    size_t i = ((size_t)blockIdx.x * 256 + threadIdx.x) * 4;
    int t0 = (int)(i & (TT - 1));
    float4 v = *(const float4*)&X[i];
    float4 m = *(const float4*)&g_tmean[t0];
    float4 r = *(const float4*)&g_trstd[t0];
    v.x = (v.x - m.x) * r.x; v.y = (v.y - m.y) * r.y;
    v.z = (v.z - m.z) * r.z; v.w = (v.w - m.w) * r.w;
    *(float4*)&Y[i] = v;
}

// ---------------- output transpose: out[b,t,f] = X[f,b,t] -----------------
__global__ void k_transpose_out(const float* __restrict__ X, float* __restrict__ out) {
    __shared__ float tile[32][33];
    int b = blockIdx.z;
    int t0 = blockIdx.x * 32, f0 = blockIdx.y * 32;
    int tx = threadIdx.x, ty = threadIdx.y;
    #pragma unroll
    for (int i = ty; i < 32; i += 8)
        tile[i][tx] = X[((size_t)(f0 + i) * BB + b) * TT + t0 + tx];
    __syncthreads();
    #pragma unroll
    for (int i = ty; i < 32; i += 8)
        out[((size_t)b * TT + t0 + i) * CC + f0 + tx] = tile[tx][i];
}

// ---------------- launch --------------------------------------------------
extern "C" void kernel_launch(void* const* d_in, const int* in_sizes, int n_in,
                              void* d_out, int out_size) {
    const float* x     = (const float*)d_in[0];
    const float* dw1_w = (const float*)d_in[1];
    const float* dw1_b = (const float*)d_in[2];
    const float* pw1_w = (const float*)d_in[3];
    const float* pw1_b = (const float*)d_in[4];
    const float* dw2_w = (const float*)d_in[5];
    const float* dw2_b = (const float*)d_in[6];
    const float* pw2_w = (const float*)d_in[7];
    const float* pw2_b = (const float*)d_in[8];
    const float* wq = (const float*)d_in[9];
    const float* bq = (const float*)d_in[10];
    const float* wk = (const float*)d_in[11];
    const float* bk = (const float*)d_in[12];
    const float* wv = (const float*)d_in[13];
    const float* bv = (const float*)d_in[14];
    const float* wp = (const float*)d_in[15];
    const float* bp = (const float*)d_in[16];
    const float* ff_w = (const float*)d_in[17];
    const float* ff_b = (const float*)d_in[18];
    float* out = (float*)d_out;

    float *pX, *pY, *pD, *pQ, *pK, *pV;
    cudaGetSymbolAddress((void**)&pX, gX);
    cudaGetSymbolAddress((void**)&pY, gY);
    cudaGetSymbolAddress((void**)&pD, gD);
    cudaGetSymbolAddress((void**)&pQ, gQ);
    cudaGetSymbolAddress((void**)&pK, gK);
    cudaGetSymbolAddress((void**)&pV, gV);

    cudaFuncSetAttribute(k_attn, cudaFuncAttributeMaxDynamicSharedMemorySize, ATTN_SMEM_BYTES);

    // 0) input transpose + positional encoding
    k_transpose_in<<<dim3(TT / 32, CC / 32, BB), dim3(32, 8)>>>(x, pX);

    // 1) conv block 1: X = pw1 @ dwconv1(LN_b(X)) + b
    k_bstats<<<dim3(32, 32), 256>>>(pX);
    k_bfinal<<<1, 32>>>();
    k_dwconv<<<dim3(CC, BB), 256>>>(pX, dw1_w, dw1_b, pD);
    k_sgemm<0><<<dim3(4, 512), 256>>>(pw1_w, pD, pw1_b, pX);

    // 2) conv blocks 2..4 (shared weights): X += pw2 @ dwconv2(LN_b(X)) + b
    for (int it = 0; it < 3; it++) {
        k_bstats<<<dim3(32, 32), 256>>>(pX);
        k_bfinal<<<1, 32>>>();
        k_dwconv<<<dim3(CC, BB), 256>>>(pX, dw2_w, dw2_b, pD);
        k_sgemm<1><<<dim3(4, 512), 256>>>(pw2_w, pD, pw2_b, pX);
    }

    // 3) attention over batch axis
    k_bstats<<<dim3(32, 32), 256>>>(pX);
    k_bfinal<<<1, 32>>>();
    k_normb<<<33554432 / 1024, 256>>>(pX, pY);
    k_sgemm<0><<<dim3(4, 512), 256>>>(wq, pY, bq, pQ);
    k_sgemm<0><<<dim3(4, 512), 256>>>(wk, pY, bk, pK);
    k_sgemm<0><<<dim3(4, 512), 256>>>(wv, pY, bv, pV);
    k_attn<<<dim3(TT / AT, HH), 256, ATTN_SMEM_BYTES>>>(pQ, pK, pV, pD);
    k_sgemm<1><<<dim3(4, 512), 256>>>(wp, pD, bp, pX);

    // 4) FF with per-t LN: X += ff_w @ LN_t(X) + ff_b
    k_tstats<<<dim3(TT / 32, 8), dim3(32, 8)>>>(pX);
    k_tfinal<<<TT / 256, 256>>>();
    k_normt<<<33554432 / 1024, 256>>>(pX, pY);
    k_sgemm<1><<<dim3(4, 512), 256>>>(ff_w, pY, ff_b, pX);

    // 5) output transpose
    k_transpose_out<<<dim3(TT / 32, CC / 32, BB), dim3(32, 8)>>>(pX, out);

    (void)in_sizes; (void)n_in; (void)out_size;
}

// round 3
// speedup vs baseline: 1.6282x; 1.6282x over previous
#include <cuda_runtime.h>
#include <cuda_bf16.h>
#include <cstdint>
#include <math.h>

// ---------------- problem constants ----------------
#define BB 32
#define TT 2048
#define CC 512          // E == F == 512
#define NN 65536        // B*T
#define HH 8
#define EPS 1e-5
#define KTOT 1536       // 3-term split-precision K: [Ah|Ah|Al] x [Bh|Bl|Bh]

// ---------------- scratch (device globals; allocation-free rule) ----------
__device__ float gX[33554432];   // state, layout (C, B, T)
__device__ float gD[33554432];   // dwconv out / attention out
__device__ float gQ[33554432];
__device__ float gK[33554432];
__device__ float gV[33554432];
__device__ __nv_bfloat16 gBt[100663296];  // B operand, [65536][1536]
__device__ __nv_bfloat16 gWb[786432];     // W operand, [512][1536]
__device__ __nv_bfloat16 gWb2[786432];    // pw2 weights (converted once)

__device__ double g_bpart[32 * 32 * 2];      // per-batch partial (sum, sumsq)
__device__ float  g_bmean[32], g_brstd[32];
__device__ double g_tpart[2048 * 8 * 2];     // per-t partial (sum, sumsq)
__device__ float  g_tmean[2048], g_trstd[2048];

// ================= helpers =================
__device__ __forceinline__ uint32_t smem_u32(const void* p) {
    uint32_t a;
    asm("{ .reg .u64 t; cvta.to.shared.u64 t, %1; cvt.u32.u64 %0, t; }" : "=r"(a) : "l"(p));
    return a;
}
__device__ __forceinline__ void cp_async16(uint32_t smaddr, const void* g) {
    asm volatile("cp.async.cg.shared.global [%0], [%1], 16;" :: "r"(smaddr), "l"(g));
}
#define CP_COMMIT() asm volatile("cp.async.commit_group;" ::: "memory")
#define CP_WAIT1()  asm volatile("cp.async.wait_group 1;" ::: "memory")

__device__ __forceinline__ void ldmatrix_x4(uint32_t& r0, uint32_t& r1, uint32_t& r2,
                                            uint32_t& r3, uint32_t addr) {
    asm volatile("ldmatrix.sync.aligned.m8n8.x4.shared.b16 {%0,%1,%2,%3}, [%4];"
        : "=r"(r0), "=r"(r1), "=r"(r2), "=r"(r3) : "r"(addr));
}
__device__ __forceinline__ void mma16816(float* d, const uint32_t* a, uint32_t b0, uint32_t b1) {
    asm volatile(
        "mma.sync.aligned.m16n8k16.row.col.f32.bf16.bf16.f32 "
        "{%0,%1,%2,%3}, {%4,%5,%6,%7}, {%8,%9}, {%0,%1,%2,%3};"
        : "+f"(d[0]), "+f"(d[1]), "+f"(d[2]), "+f"(d[3])
        : "r"(a[0]), "r"(a[1]), "r"(a[2]), "r"(a[3]), "r"(b0), "r"(b1));
}

// ---------------- input transpose + positional encoding -------------------
__global__ void k_transpose_in(const float* __restrict__ in, float* __restrict__ X) {
    __shared__ float tile[32][33];
    int b = blockIdx.z;
    int t0 = blockIdx.x * 32, c0 = blockIdx.y * 32;
    int tx = threadIdx.x, ty = threadIdx.y;
    #pragma unroll
    for (int i = ty; i < 32; i += 8)
        tile[i][tx] = in[((size_t)b * TT + t0 + i) * CC + c0 + tx];
    __syncthreads();
    #pragma unroll
    for (int i = ty; i < 32; i += 8) {
        int c = c0 + i;
        float div = expf((float)(c & ~1) * (-9.210340371976184f / 512.0f));
        float ang = (float)b * div;
        float pe = (c & 1) ? cosf(ang) : sinf(ang);
        X[((size_t)c * BB + b) * TT + t0 + tx] = tile[tx][i] + pe;
    }
}

// ---------------- per-batch LN stats ----------------
__global__ void k_bstats(const float* __restrict__ X) {
    int b = blockIdx.x, cy = blockIdx.y;
    int tid = threadIdx.x;
    double s = 0, q = 0;
    for (int c = cy * 16; c < cy * 16 + 16; c++) {
        const float* row = X + ((size_t)c * BB + b) * TT;
        for (int t = tid; t < TT; t += 256) { float v = row[t]; s += v; q += (double)v * v; }
    }
    __shared__ double ss[256], qq[256];
    ss[tid] = s; qq[tid] = q; __syncthreads();
    for (int o = 128; o > 0; o >>= 1) {
        if (tid < o) { ss[tid] += ss[tid + o]; qq[tid] += qq[tid + o]; }
        __syncthreads();
    }
    if (tid == 0) {
        g_bpart[(b * 32 + cy) * 2] = ss[0];
        g_bpart[(b * 32 + cy) * 2 + 1] = qq[0];
    }
}

__global__ void k_bfinal() {
    int b = threadIdx.x;
    if (b < 32) {
        double s = 0, q = 0;
        for (int i = 0; i < 32; i++) { s += g_bpart[(b * 32 + i) * 2]; q += g_bpart[(b * 32 + i) * 2 + 1]; }
        double n = 1048576.0;
        double mu = s / n;
        double var = q / n - mu * mu;
        g_bmean[b] = (float)mu;
        g_brstd[b] = (float)(1.0 / sqrt(var + (double)EPS));
    }
}

// ---------------- fused per-batch-LN + depthwise conv (k=7) --------
__global__ void k_dwconv(const float* __restrict__ X, const float* __restrict__ dww,
                         const float* __restrict__ dwb, float* __restrict__ D) {
    int c = blockIdx.x, b = blockIdx.y;
    int tid = threadIdx.x;
    __shared__ float s[TT + 8];
    float mu = g_bmean[b], r = g_brstd[b];
    const float* row = X + ((size_t)c * BB + b) * TT;
    for (int t = tid; t < TT; t += 256) s[t + 3] = (row[t] - mu) * r;
    if (tid < 3) { s[tid] = 0.0f; s[TT + 3 + tid] = 0.0f; }
    __syncthreads();
    float w0 = dww[c * 7 + 0], w1 = dww[c * 7 + 1], w2 = dww[c * 7 + 2], w3 = dww[c * 7 + 3];
    float w4 = dww[c * 7 + 4], w5 = dww[c * 7 + 5], w6 = dww[c * 7 + 6];
    float bias = dwb[c];
    float* drow = D + ((size_t)c * BB + b) * TT;
    for (int t = tid; t < TT; t += 256) {
        float acc = bias;
        acc += w0 * s[t + 0]; acc += w1 * s[t + 1]; acc += w2 * s[t + 2];
        acc += w3 * s[t + 3]; acc += w4 * s[t + 4]; acc += w5 * s[t + 5];
        acc += w6 * s[t + 6];
        drow[t] = acc;
    }
}

// ---------------- B-operand convert: fp32 [512][65536] -> bf16 [65536][1536]
// row n layout: [Bh(512) | Bl(512) | Bh(512)]
// MODE 0: plain; MODE 1: per-batch LN; MODE 2: per-t LN
template <int MODE>
__global__ void k_cvtB(const float* __restrict__ X, __nv_bfloat16* __restrict__ Bt) {
    __shared__ float tile[32][33];
    int n0 = blockIdx.x * 32, k0 = blockIdx.y * 32;
    int tx = threadIdx.x, ty = threadIdx.y;
    int n = n0 + tx;
    float mu = 0.0f, sc = 1.0f;
    if (MODE == 1) { int b = n >> 11; mu = g_bmean[b]; sc = g_brstd[b]; }
    if (MODE == 2) { int t = n & (TT - 1); mu = g_tmean[t]; sc = g_trstd[t]; }
    #pragma unroll
    for (int i = ty; i < 32; i += 8)
        tile[i][tx] = (X[(size_t)(k0 + i) * NN + n] - mu) * sc;
    __syncthreads();
    #pragma unroll
    for (int i = ty; i < 32; i += 8) {
        float v = tile[tx][i];
        __nv_bfloat16 h = __float2bfloat16(v);
        __nv_bfloat16 l = __float2bfloat16(v - __bfloat162float(h));
        size_t ro = (size_t)(n0 + i) * KTOT + k0 + tx;
        Bt[ro] = h;
        Bt[ro + 512] = l;
        Bt[ro + 1024] = h;
    }
}

// ---------------- W-operand convert: fp32 [512][512] -> bf16 [512][1536]
// row m layout: [Wh | Wh | Wl]
__global__ void k_cvtW(const float* __restrict__ W, __nv_bfloat16* __restrict__ Wb) {
    int idx = blockIdx.x * 256 + threadIdx.x;
    float v = W[idx];
    int m = idx >> 9, k = idx & 511;
    __nv_bfloat16 h = __float2bfloat16(v);
    __nv_bfloat16 l = __float2bfloat16(v - __bfloat162float(h));
    size_t ro = (size_t)m * KTOT + k;
    Wb[ro] = h;
    Wb[ro + 512] = h;
    Wb[ro + 1024] = l;
}

// ---------------- tensor-core GEMM: C[512,65536] (+)= W @ X + bias ----------
// mma.sync m16n8k16 bf16. CTA tile 128x128, 8 warps (warp tile 64x32),
// 3-stage cp.async pipeline, K-stage = 64 elems (128B rows, XOR swizzle).
#define KSTAGE 64
#define NSTG 3
#define A_BYTES 16384           // 128 rows x 128 B
#define STG_BYTES 32768         // A + B
#define MMA_SMEM (NSTG * STG_BYTES)
#define NKC (KTOT / KSTAGE)     // 24 k-chunks

template <int BETA>
__global__ void __launch_bounds__(256, 2)
k_mma(const __nv_bfloat16* __restrict__ Wb, const __nv_bfloat16* __restrict__ Bt,
      const float* __restrict__ bias, float* __restrict__ C) {
    extern __shared__ char dsm[];
    uint32_t smb = smem_u32(dsm);
    int tid = threadIdx.x;
    int wid = tid >> 5, lane = tid & 31;
    int m0 = blockIdx.x * 128, n0 = blockIdx.y * 128;
    int warp_m = wid >> 2, warp_n = wid & 3;   // 2 x 4 warps, warp tile 64x32

    // per-thread load indices (4 x 16B per operand per stage)
    int ldrow = tid >> 3, ldc = tid & 7;       // rows 0..31 step via +32

    float acc[4][4][4];
    #pragma unroll
    for (int a = 0; a < 4; a++)
        #pragma unroll
        for (int b = 0; b < 4; b++)
            #pragma unroll
            for (int c = 0; c < 4; c++) acc[a][b][c] = 0.0f;

    // prefetch helper (macro-ish lambda)
    auto prefetch = [&](int st, int kc) {
        uint32_t sA = smb + st * STG_BYTES;
        const __nv_bfloat16* gA = Wb + (size_t)m0 * KTOT + kc * KSTAGE;
        const __nv_bfloat16* gB = Bt + (size_t)n0 * KTOT + kc * KSTAGE;
        #pragma unroll
        for (int i = 0; i < 4; i++) {
            int row = ldrow + i * 32;
            uint32_t sw = (uint32_t)(row * 128 + ((ldc ^ (row & 7)) << 4));
            cp_async16(sA + sw, gA + (size_t)row * KTOT + ldc * 8);
            cp_async16(sA + A_BYTES + sw, gB + (size_t)row * KTOT + ldc * 8);
        }
    };

    prefetch(0, 0); CP_COMMIT();
    prefetch(1, 1); CP_COMMIT();

    int lr = lane & 7, lq = lane >> 3;
    int rowoff = lr + (lq & 1) * 8;
    int csel = lq >> 1;

    for (int i = 0; i < NKC; i++) {
        CP_WAIT1();
        __syncthreads();
        if (i + 2 < NKC) prefetch((i + 2) % NSTG, i + 2);
        CP_COMMIT();

        uint32_t sA = smb + (i % NSTG) * STG_BYTES;
        uint32_t sB = sA + A_BYTES;
        #pragma unroll
        for (int kk = 0; kk < 4; kk++) {
            uint32_t af[4][4], bf[2][4];
            int chnk = kk * 2 + csel;
            #pragma unroll
            for (int mf = 0; mf < 4; mf++) {
                int row = warp_m * 64 + mf * 16 + rowoff;
                uint32_t addr = sA + row * 128 + ((chnk ^ (row & 7)) << 4);
                ldmatrix_x4(af[mf][0], af[mf][1], af[mf][2], af[mf][3], addr);
            }
            #pragma unroll
            for (int nf = 0; nf < 2; nf++) {
                int row = warp_n * 32 + nf * 16 + rowoff;
                uint32_t addr = sB + row * 128 + ((chnk ^ (row & 7)) << 4);
                ldmatrix_x4(bf[nf][0], bf[nf][1], bf[nf][2], bf[nf][3], addr);
            }
            #pragma unroll
            for (int mf = 0; mf < 4; mf++)
                #pragma unroll
                for (int t = 0; t < 4; t++)
                    mma16816(acc[mf][t], af[mf], bf[t >> 1][t & 1], bf[t >> 1][(t & 1) + 2]);
        }
        __syncthreads();
    }

    // epilogue: direct global stores (float2), fused bias (+ residual)
    int g = lane >> 2, tg = lane & 3;
    #pragma unroll
    for (int mf = 0; mf < 4; mf++) {
        int mA = m0 + warp_m * 64 + mf * 16 + g;
        int mB2 = mA + 8;
        float bva = bias[mA], bvb = bias[mB2];
        #pragma unroll
        for (int t = 0; t < 4; t++) {
            int n = n0 + warp_n * 32 + t * 8 + tg * 2;
            size_t o0 = (size_t)mA * NN + n;
            size_t o1 = (size_t)mB2 * NN + n;
            float2 v0 = { acc[mf][t][0] + bva, acc[mf][t][1] + bva };
            float2 v1 = { acc[mf][t][2] + bvb, acc[mf][t][3] + bvb };
            if (BETA) {
                float2 p0 = *(const float2*)&C[o0];
                float2 p1 = *(const float2*)&C[o1];
                v0.x += p0.x; v0.y += p0.y;
                v1.x += p1.x; v1.y += p1.y;
            }
            *(float2*)&C[o0] = v0;
            *(float2*)&C[o1] = v1;
        }
    }
}

// ---------------- attention over the batch axis ----------
#define AT 8
#define SQ_OFF 0
#define SK_OFF 16384
#define SV_OFF 32768
#define ST_OFF 51200
#define ATTN_SMEM_FLOATS (16384 + 16384 + 18432 + 1056)
#define ATTN_SMEM_BYTES (ATTN_SMEM_FLOATS * 4)

__global__ void k_attn(const float* __restrict__ Q, const float* __restrict__ Kg,
                       const float* __restrict__ Vg, float* __restrict__ O) {
    extern __shared__ float sm[];
    float* smq = sm + SQ_OFF;
    float* smk = sm + SK_OFF;
    float* smv = sm + SV_OFF;
    float* st  = sm + ST_OFF;
    int h = blockIdx.y;
    int t0 = blockIdx.x * AT;
    int tid = threadIdx.x;

    for (int p0 = tid; p0 < 2048; p0 += 256) {
        int d = p0 >> 5, b = p0 & 31;
        size_t base = ((size_t)(h * 64 + d) * 32 + b) * 2048 + t0;
        float4 a0 = *(const float4*)&Q[base];  float4 a1 = *(const float4*)&Q[base + 4];
        float4 k0 = *(const float4*)&Kg[base]; float4 k1 = *(const float4*)&Kg[base + 4];
        float4 v0 = *(const float4*)&Vg[base]; float4 v1 = *(const float4*)&Vg[base + 4];
        float qa[8] = {a0.x, a0.y, a0.z, a0.w, a1.x, a1.y, a1.z, a1.w};
        float ka[8] = {k0.x, k0.y, k0.z, k0.w, k1.x, k1.y, k1.z, k1.w};
        float va[8] = {v0.x, v0.y, v0.z, v0.w, v1.x, v1.y, v1.z, v1.w};
        #pragma unroll
        for (int s = 0; s < 8; s++) {
            smq[(s * 64 + d) * 32 + b] = qa[s];
            smk[(s * 64 + d) * 32 + b] = ka[s];
            smv[(s * 64 + d) * 36 + b] = va[s];
        }
    }
    __syncthreads();

    const float scale = 0.125f;
    int sb = tid >> 3, sp0 = (tid & 7) * 4;
    for (int ttk = 0; ttk < AT; ttk++) {
        float a0 = 0, a1 = 0, a2 = 0, a3 = 0;
        #pragma unroll
        for (int d = 0; d < 64; d++) {
            float qv = smq[(ttk * 64 + d) * 32 + sb];
            float4 kv = *(const float4*)&smk[(ttk * 64 + d) * 32 + sp0];
            a0 += qv * kv.x; a1 += qv * kv.y; a2 += qv * kv.z; a3 += qv * kv.w;
        }
        st[sb * 33 + sp0 + 0] = a0 * scale;
        st[sb * 33 + sp0 + 1] = a1 * scale;
        st[sb * 33 + sp0 + 2] = a2 * scale;
        st[sb * 33 + sp0 + 3] = a3 * scale;
        __syncthreads();
        if (tid < 32) {
            const float* row = st + tid * 33;
            float mx = -1e30f;
            #pragma unroll
            for (int j = 0; j < 32; j++) mx = fmaxf(mx, row[j]);
            float ev[32]; float sum = 0.0f;
            #pragma unroll
            for (int j = 0; j < 32; j++) { ev[j] = expf(row[j] - mx); sum += ev[j]; }
            float inv = 1.0f / sum;
            #pragma unroll
            for (int j = 0; j < 32; j++) smq[ttk * 1152 + tid * 36 + j] = ev[j] * inv;
        }
        __syncthreads();
    }

    for (int rep = 0; rep < 8; rep++) {
        int o = tid + rep * 256;
        int ob = o >> 6, od = o & 63;
        float outv[8];
        #pragma unroll
        for (int s = 0; s < 8; s++) {
            float acc = 0.0f;
            #pragma unroll
            for (int bp = 0; bp < 32; bp += 4) {
                float4 pv = *(const float4*)&smq[s * 1152 + ob * 36 + bp];
                float4 vv = *(const float4*)&smv[(s * 64 + od) * 36 + bp];
                acc += pv.x * vv.x + pv.y * vv.y + pv.z * vv.z + pv.w * vv.w;
            }
            outv[s] = acc;
        }
        size_t base = ((size_t)(h * 64 + od) * 32 + ob) * 2048 + t0;
        float4 w0 = {outv[0], outv[1], outv[2], outv[3]};
        float4 w1 = {outv[4], outv[5], outv[6], outv[7]};
        *(float4*)&O[base] = w0;
        *(float4*)&O[base + 4] = w1;
    }
}

// ---------------- per-t LN stats ----------------
__global__ void k_tstats(const float* __restrict__ X) {
    int t = blockIdx.x * 32 + threadIdx.x;
    int ry = blockIdx.y;
    double s = 0, q = 0;
    for (int r = ry * 2048 + threadIdx.y; r < (ry + 1) * 2048; r += 8) {
        float v = X[(size_t)r * TT + t];
        s += v; q += (double)v * v;
    }
    __shared__ double ss[8][32], qq[8][32];
    ss[threadIdx.y][threadIdx.x] = s;
    qq[threadIdx.y][threadIdx.x] = q;
    __syncthreads();
    if (threadIdx.y == 0) {
        double S = 0, Qq = 0;
        #pragma unroll
        for (int j = 0; j < 8; j++) { S += ss[j][threadIdx.x]; Qq += qq[j][threadIdx.x]; }
        g_tpart[(t * 8 + ry) * 2] = S;
        g_tpart[(t * 8 + ry) * 2 + 1] = Qq;
    }
}

__global__ void k_tfinal() {
    int t = blockIdx.x * 256 + threadIdx.x;
    double s = 0, q = 0;
    for (int i = 0; i < 8; i++) { s += g_tpart[(t * 8 + i) * 2]; q += g_tpart[(t * 8 + i) * 2 + 1]; }
    double n = 16384.0;
    double mu = s / n;
    double var = q / n - mu * mu;
    g_tmean[t] = (float)mu;
    g_trstd[t] = (float)(1.0 / sqrt(var + (double)EPS));
}

// ---------------- output transpose ----------------
__global__ void k_transpose_out(const float* __restrict__ X, float* __restrict__ out) {
    __shared__ float tile[32][33];
    int b = blockIdx.z;
    int t0 = blockIdx.x * 32, f0 = blockIdx.y * 32;
    int tx = threadIdx.x, ty = threadIdx.y;
    #pragma unroll
    for (int i = ty; i < 32; i += 8)
        tile[i][tx] = X[((size_t)(f0 + i) * BB + b) * TT + t0 + tx];
    __syncthreads();
    #pragma unroll
    for (int i = ty; i < 32; i += 8)
        out[((size_t)b * TT + t0 + i) * CC + f0 + tx] = tile[tx][i];
}

// ---------------- launch --------------------------------------------------
extern "C" void kernel_launch(void* const* d_in, const int* in_sizes, int n_in,
                              void* d_out, int out_size) {
    const float* x     = (const float*)d_in[0];
    const float* dw1_w = (const float*)d_in[1];
    const float* dw1_b = (const float*)d_in[2];
    const float* pw1_w = (const float*)d_in[3];
    const float* pw1_b = (const float*)d_in[4];
    const float* dw2_w = (const float*)d_in[5];
    const float* dw2_b = (const float*)d_in[6];
    const float* pw2_w = (const float*)d_in[7];
    const float* pw2_b = (const float*)d_in[8];
    const float* wq = (const float*)d_in[9];
    const float* bq = (const float*)d_in[10];
    const float* wk = (const float*)d_in[11];
    const float* bk = (const float*)d_in[12];
    const float* wv = (const float*)d_in[13];
    const float* bv = (const float*)d_in[14];
    const float* wp = (const float*)d_in[15];
    const float* bp = (const float*)d_in[16];
    const float* ff_w = (const float*)d_in[17];
    const float* ff_b = (const float*)d_in[18];
    float* out = (float*)d_out;

    float *pX, *pD, *pQ, *pK, *pV;
    __nv_bfloat16 *pBt, *pWb, *pWb2;
    cudaGetSymbolAddress((void**)&pX, gX);
    cudaGetSymbolAddress((void**)&pD, gD);
    cudaGetSymbolAddress((void**)&pQ, gQ);
    cudaGetSymbolAddress((void**)&pK, gK);
    cudaGetSymbolAddress((void**)&pV, gV);
    cudaGetSymbolAddress((void**)&pBt, gBt);
    cudaGetSymbolAddress((void**)&pWb, gWb);
    cudaGetSymbolAddress((void**)&pWb2, gWb2);

    cudaFuncSetAttribute(k_attn, cudaFuncAttributeMaxDynamicSharedMemorySize, ATTN_SMEM_BYTES);
    cudaFuncSetAttribute(k_mma<0>, cudaFuncAttributeMaxDynamicSharedMemorySize, MMA_SMEM);
    cudaFuncSetAttribute(k_mma<1>, cudaFuncAttributeMaxDynamicSharedMemorySize, MMA_SMEM);

    dim3 cvtG(NN / 32, CC / 32), cvtB32(32, 8);
    dim3 mmaG(4, 512);   // m fast -> B tiles shared across m in L2

    // 0) input transpose + positional encoding
    k_transpose_in<<<dim3(TT / 32, CC / 32, BB), dim3(32, 8)>>>(x, pX);

    // 1) conv block 1: X = pw1 @ dwconv1(LN_b(X)) + b
    k_bstats<<<dim3(32, 32), 256>>>(pX);
    k_bfinal<<<1, 32>>>();
    k_dwconv<<<dim3(CC, BB), 256>>>(pX, dw1_w, dw1_b, pD);
    k_cvtB<0><<<cvtG, cvtB32>>>(pD, pBt);
    k_cvtW<<<1024, 256>>>(pw1_w, pWb);
    k_mma<0><<<mmaG, 256, MMA_SMEM>>>(pWb, pBt, pw1_b, pX);

    // 2) conv blocks 2..4 (shared weights): X += pw2 @ dwconv2(LN_b(X)) + b
    k_cvtW<<<1024, 256>>>(pw2_w, pWb2);
    for (int it = 0; it < 3; it++) {
        k_bstats<<<dim3(32, 32), 256>>>(pX);
        k_bfinal<<<1, 32>>>();
        k_dwconv<<<dim3(CC, BB), 256>>>(pX, dw2_w, dw2_b, pD);
        k_cvtB<0><<<cvtG, cvtB32>>>(pD, pBt);
        k_mma<1><<<mmaG, 256, MMA_SMEM>>>(pWb2, pBt, pw2_b, pX);
    }

    // 3) attention over batch axis
    k_bstats<<<dim3(32, 32), 256>>>(pX);
    k_bfinal<<<1, 32>>>();
    k_cvtB<1><<<cvtG, cvtB32>>>(pX, pBt);    // Y = LN_b(X), fused into convert
    k_cvtW<<<1024, 256>>>(wq, pWb);
    k_mma<0><<<mmaG, 256, MMA_SMEM>>>(pWb, pBt, bq, pQ);
    k_cvtW<<<1024, 256>>>(wk, pWb);
    k_mma<0><<<mmaG, 256, MMA_SMEM>>>(pWb, pBt, bk, pK);
    k_cvtW<<<1024, 256>>>(wv, pWb);
    k_mma<0><<<mmaG, 256, MMA_SMEM>>>(pWb, pBt, bv, pV);
    k_attn<<<dim3(TT / AT, HH), 256, ATTN_SMEM_BYTES>>>(pQ, pK, pV, pD);
    k_cvtB<0><<<cvtG, cvtB32>>>(pD, pBt);
    k_cvtW<<<1024, 256>>>(wp, pWb);
    k_mma<1><<<mmaG, 256, MMA_SMEM>>>(pWb, pBt, bp, pX);

    // 4) FF with per-t LN: X += ff_w @ LN_t(X) + ff_b
    k_tstats<<<dim3(TT / 32, 8), dim3(32, 8)>>>(pX);
    k_tfinal<<<TT / 256, 256>>>();
    k_cvtB<2><<<cvtG, cvtB32>>>(pX, pBt);    // Y = LN_t(X), fused into convert
    k_cvtW<<<1024, 256>>>(ff_w, pWb);
    k_mma<1><<<mmaG, 256, MMA_SMEM>>>(pWb, pBt, ff_b, pX);

    // 5) output transpose
    k_transpose_out<<<dim3(TT / 32, CC / 32, BB), dim3(32, 8)>>>(pX, out);

    (void)in_sizes; (void)n_in; (void)out_size;
}

// round 4
// speedup vs baseline: 1.9835x; 1.2182x over previous
#include <cuda_runtime.h>
#include <cuda_fp16.h>
#include <cstdint>
#include <math.h>

// ---------------- problem constants ----------------
#define BB 32
#define TT 2048
#define CC 512          // E == F == 512
#define NN 65536        // B*T
#define HH 8
#define EPS 1e-5

// ---------------- scratch (device globals; allocation-free rule) ----------
__device__ float gX[33554432];   // state, layout (C, B, T)
__device__ float gD[33554432];   // dwconv out / attention out
__device__ float gQ[33554432];
__device__ float gK[33554432];
__device__ float gV[33554432];
__device__ __half gBt[33554432];  // B operand, [65536][512] fp16
__device__ __half gWb[524288];    // W operand, [512][1024] = [Wh | Wl]
__device__ __half gWb2[524288];   // pw2 weights (converted once)

__device__ double g_bpart[32 * 32 * 2];      // per-batch partial (sum, sumsq)
__device__ float  g_bmean[32], g_brstd[32];
__device__ double g_tpart[2048 * 8 * 2];     // per-t partial (sum, sumsq)
__device__ float  g_tmean[2048], g_trstd[2048];

// ================= helpers =================
__device__ __forceinline__ uint32_t smem_u32(const void* p) {
    uint32_t a;
    asm("{ .reg .u64 t; cvta.to.shared.u64 t, %1; cvt.u32.u64 %0, t; }" : "=r"(a) : "l"(p));
    return a;
}
__device__ __forceinline__ void cp_async16(uint32_t smaddr, const void* g) {
    asm volatile("cp.async.cg.shared.global [%0], [%1], 16;" :: "r"(smaddr), "l"(g));
}
#define CP_COMMIT() asm volatile("cp.async.commit_group;" ::: "memory")
#define CP_WAIT1()  asm volatile("cp.async.wait_group 1;" ::: "memory")

__device__ __forceinline__ void ldmatrix_x4(uint32_t& r0, uint32_t& r1, uint32_t& r2,
                                            uint32_t& r3, uint32_t addr) {
    asm volatile("ldmatrix.sync.aligned.m8n8.x4.shared.b16 {%0,%1,%2,%3}, [%4];"
        : "=r"(r0), "=r"(r1), "=r"(r2), "=r"(r3) : "r"(addr));
}
__device__ __forceinline__ void mma16816(float* d, const uint32_t* a, uint32_t b0, uint32_t b1) {
    asm volatile(
        "mma.sync.aligned.m16n8k16.row.col.f32.f16.f16.f32 "
        "{%0,%1,%2,%3}, {%4,%5,%6,%7}, {%8,%9}, {%0,%1,%2,%3};"
        : "+f"(d[0]), "+f"(d[1]), "+f"(d[2]), "+f"(d[3])
        : "r"(a[0]), "r"(a[1]), "r"(a[2]), "r"(a[3]), "r"(b0), "r"(b1));
}

// ---------------- input transpose + positional encoding -------------------
__global__ void k_transpose_in(const float* __restrict__ in, float* __restrict__ X) {
    __shared__ float tile[32][33];
    int b = blockIdx.z;
    int t0 = blockIdx.x * 32, c0 = blockIdx.y * 32;
    int tx = threadIdx.x, ty = threadIdx.y;
    #pragma unroll
    for (int i = ty; i < 32; i += 8)
        tile[i][tx] = in[((size_t)b * TT + t0 + i) * CC + c0 + tx];
    __syncthreads();
    #pragma unroll
    for (int i = ty; i < 32; i += 8) {
        int c = c0 + i;
        float div = expf((float)(c & ~1) * (-9.210340371976184f / 512.0f));
        float ang = (float)b * div;
        float pe = (c & 1) ? cosf(ang) : sinf(ang);
        X[((size_t)c * BB + b) * TT + t0 + tx] = tile[tx][i] + pe;
    }
}

// ---------------- per-batch LN stats ----------------
__global__ void k_bstats(const float* __restrict__ X) {
    int b = blockIdx.x, cy = blockIdx.y;
    int tid = threadIdx.x;
    double s = 0, q = 0;
    for (int c = cy * 16; c < cy * 16 + 16; c++) {
        const float* row = X + ((size_t)c * BB + b) * TT;
        for (int t = tid; t < TT; t += 256) { float v = row[t]; s += v; q += (double)v * v; }
    }
    __shared__ double ss[256], qq[256];
    ss[tid] = s; qq[tid] = q; __syncthreads();
    for (int o = 128; o > 0; o >>= 1) {
        if (tid < o) { ss[tid] += ss[tid + o]; qq[tid] += qq[tid + o]; }
        __syncthreads();
    }
    if (tid == 0) {
        g_bpart[(b * 32 + cy) * 2] = ss[0];
        g_bpart[(b * 32 + cy) * 2 + 1] = qq[0];
    }
}

__global__ void k_bfinal() {
    int b = threadIdx.x;
    if (b < 32) {
        double s = 0, q = 0;
        for (int i = 0; i < 32; i++) { s += g_bpart[(b * 32 + i) * 2]; q += g_bpart[(b * 32 + i) * 2 + 1]; }
        double n = 1048576.0;
        double mu = s / n;
        double var = q / n - mu * mu;
        g_bmean[b] = (float)mu;
        g_brstd[b] = (float)(1.0 / sqrt(var + (double)EPS));
    }
}

// ---------------- fused per-batch-LN + depthwise conv (k=7) --------
__global__ void k_dwconv(const float* __restrict__ X, const float* __restrict__ dww,
                         const float* __restrict__ dwb, float* __restrict__ D) {
    int c = blockIdx.x, b = blockIdx.y;
    int tid = threadIdx.x;
    __shared__ float s[TT + 8];
    float mu = g_bmean[b], r = g_brstd[b];
    const float* row = X + ((size_t)c * BB + b) * TT;
    for (int t = tid; t < TT; t += 256) s[t + 3] = (row[t] - mu) * r;
    if (tid < 3) { s[tid] = 0.0f; s[TT + 3 + tid] = 0.0f; }
    __syncthreads();
    float w0 = dww[c * 7 + 0], w1 = dww[c * 7 + 1], w2 = dww[c * 7 + 2], w3 = dww[c * 7 + 3];
    float w4 = dww[c * 7 + 4], w5 = dww[c * 7 + 5], w6 = dww[c * 7 + 6];
    float bias = dwb[c];
    float* drow = D + ((size_t)c * BB + b) * TT;
    for (int t = tid; t < TT; t += 256) {
        float acc = bias;
        acc += w0 * s[t + 0]; acc += w1 * s[t + 1]; acc += w2 * s[t + 2];
        acc += w3 * s[t + 3]; acc += w4 * s[t + 4]; acc += w5 * s[t + 5];
        acc += w6 * s[t + 6];
        drow[t] = acc;
    }
}

// ---------------- B-operand convert: fp32 [512][65536] -> fp16 [65536][512]
// MODE 0: plain; MODE 1: per-batch LN; MODE 2: per-t LN
template <int MODE>
__global__ void k_cvtB(const float* __restrict__ X, __half* __restrict__ Bt) {
    __shared__ float tile[32][33];
    int n0 = blockIdx.x * 32, k0 = blockIdx.y * 32;
    int tx = threadIdx.x, ty = threadIdx.y;
    int n = n0 + tx;
    float mu = 0.0f, sc = 1.0f;
    if (MODE == 1) { int b = n >> 11; mu = g_bmean[b]; sc = g_brstd[b]; }
    if (MODE == 2) { int t = n & (TT - 1); mu = g_tmean[t]; sc = g_trstd[t]; }
    #pragma unroll
    for (int i = ty; i < 32; i += 8)
        tile[i][tx] = (X[(size_t)(k0 + i) * NN + n] - mu) * sc;
    __syncthreads();
    #pragma unroll
    for (int i = ty; i < 32; i += 8) {
        float v = tile[tx][i];
        Bt[(size_t)(n0 + i) * 512 + k0 + tx] = __float2half_rn(v);
    }
}

// ---------------- W-operand convert: fp32 [512][512] -> fp16 [512][1024] = [Wh|Wl]
__global__ void k_cvtW(const float* __restrict__ W, __half* __restrict__ Wb) {
    int idx = blockIdx.x * 256 + threadIdx.x;
    float v = W[idx];
    int m = idx >> 9, k = idx & 511;
    __half h = __float2half_rn(v);
    __half l = __float2half_rn(v - __half2float(h));
    Wb[(size_t)m * 1024 + k] = h;
    Wb[(size_t)m * 1024 + 512 + k] = l;
}

// ---------------- tensor-core GEMM: C[512,65536] (+)= W @ X + bias ----------
// fp16 2-term: A = [Wh (rows 0..127) ; Wl (rows 128..255)] per m-block, B single fp16.
// mma.sync m16n8k16. CTA tile 128x128, 8 warps (warp 64x32), K=512, chunks of 64,
// 2-stage cp.async pipeline. B fragment reused for hi and lo passes.
#define KSTAGE 64
#define NSTG 2
#define A_BYTES 32768           // 256 rows x 128 B
#define STG_BYTES 49152         // A + B(16KB)
#define MMA_SMEM (NSTG * STG_BYTES)
#define NKC 8

template <int BETA>
__global__ void __launch_bounds__(256, 2)
k_mma(const __half* __restrict__ Wb, const __half* __restrict__ Bt,
      const float* __restrict__ bias, float* __restrict__ C) {
    extern __shared__ char dsm[];
    uint32_t smb = smem_u32(dsm);
    int tid = threadIdx.x;
    int wid = tid >> 5, lane = tid & 31;
    int m0 = blockIdx.x * 128, n0 = blockIdx.y * 128;
    int warp_m = wid >> 2, warp_n = wid & 3;   // 2 x 4 warps, warp tile 64x32

    int ldrow = tid >> 3, ldc = tid & 7;

    float acc[4][4][4];
    #pragma unroll
    for (int a = 0; a < 4; a++)
        #pragma unroll
        for (int b = 0; b < 4; b++)
            #pragma unroll
            for (int c = 0; c < 4; c++) acc[a][b][c] = 0.0f;

    auto prefetch = [&](int st, int kc) {
        uint32_t sA = smb + st * STG_BYTES;
        #pragma unroll
        for (int i = 0; i < 8; i++) {
            int row = ldrow + i * 32;   // 0..255: 0..127 = Wh, 128..255 = Wl
            const __half* g = Wb + (size_t)(m0 + (row & 127)) * 1024
                                 + (row >> 7) * 512 + kc * KSTAGE + ldc * 8;
            uint32_t sw = (uint32_t)(row * 128 + ((ldc ^ (row & 7)) << 4));
            cp_async16(sA + sw, g);
        }
        #pragma unroll
        for (int i = 0; i < 4; i++) {
            int row = ldrow + i * 32;   // 0..127
            const __half* g = Bt + (size_t)(n0 + row) * 512 + kc * KSTAGE + ldc * 8;
            uint32_t sw = (uint32_t)(row * 128 + ((ldc ^ (row & 7)) << 4));
            cp_async16(sA + A_BYTES + sw, g);
        }
    };

    prefetch(0, 0); CP_COMMIT();

    int lr = lane & 7, lq = lane >> 3;
    int rowoff = lr + (lq & 1) * 8;
    int csel = lq >> 1;

    for (int i = 0; i < NKC; i++) {
        if (i + 1 < NKC) prefetch((i + 1) & 1, i + 1);
        CP_COMMIT();
        CP_WAIT1();
        __syncthreads();

        uint32_t sA = smb + (i & 1) * STG_BYTES;
        uint32_t sB = sA + A_BYTES;
        #pragma unroll
        for (int kk = 0; kk < 4; kk++) {
            int chnk = kk * 2 + csel;
            uint32_t bf[2][4];
            #pragma unroll
            for (int nf = 0; nf < 2; nf++) {
                int row = warp_n * 32 + nf * 16 + rowoff;
                ldmatrix_x4(bf[nf][0], bf[nf][1], bf[nf][2], bf[nf][3],
                            sB + row * 128 + ((chnk ^ (row & 7)) << 4));
            }
            uint32_t af[4][4];
            // hi pass (Wh rows 0..127)
            #pragma unroll
            for (int mf = 0; mf < 4; mf++) {
                int row = warp_m * 64 + mf * 16 + rowoff;
                ldmatrix_x4(af[mf][0], af[mf][1], af[mf][2], af[mf][3],
                            sA + row * 128 + ((chnk ^ (row & 7)) << 4));
            }
            #pragma unroll
            for (int mf = 0; mf < 4; mf++)
                #pragma unroll
                for (int t = 0; t < 4; t++)
                    mma16816(acc[mf][t], af[mf], bf[t >> 1][t & 1], bf[t >> 1][(t & 1) + 2]);
            // lo pass (Wl rows 128..255), reuse af registers and bf fragments
            #pragma unroll
            for (int mf = 0; mf < 4; mf++) {
                int row = 128 + warp_m * 64 + mf * 16 + rowoff;
                ldmatrix_x4(af[mf][0], af[mf][1], af[mf][2], af[mf][3],
                            sA + row * 128 + ((chnk ^ (row & 7)) << 4));
            }
            #pragma unroll
            for (int mf = 0; mf < 4; mf++)
                #pragma unroll
                for (int t = 0; t < 4; t++)
                    mma16816(acc[mf][t], af[mf], bf[t >> 1][t & 1], bf[t >> 1][(t & 1) + 2]);
        }
        __syncthreads();
    }

    // epilogue: direct global stores (float2), fused bias (+ residual)
    int g = lane >> 2, tg = lane & 3;
    #pragma unroll
    for (int mf = 0; mf < 4; mf++) {
        int mA = m0 + warp_m * 64 + mf * 16 + g;
        int mB2 = mA + 8;
        float bva = bias[mA], bvb = bias[mB2];
        #pragma unroll
        for (int t = 0; t < 4; t++) {
            int n = n0 + warp_n * 32 + t * 8 + tg * 2;
            size_t o0 = (size_t)mA * NN + n;
            size_t o1 = (size_t)mB2 * NN + n;
            float2 v0 = { acc[mf][t][0] + bva, acc[mf][t][1] + bva };
            float2 v1 = { acc[mf][t][2] + bvb, acc[mf][t][3] + bvb };
            if (BETA) {
                float2 p0 = *(const float2*)&C[o0];
                float2 p1 = *(const float2*)&C[o1];
                v0.x += p0.x; v0.y += p0.y;
                v1.x += p1.x; v1.y += p1.y;
            }
            *(float2*)&C[o0] = v0;
            *(float2*)&C[o1] = v1;
        }
    }
}

// ---------------- attention over the batch axis ----------
#define AT 8
#define SQ_OFF 0
#define SK_OFF 16384
#define SV_OFF 32768
#define ST_OFF 51200
#define ATTN_SMEM_FLOATS (16384 + 16384 + 18432 + 1056)
#define ATTN_SMEM_BYTES (ATTN_SMEM_FLOATS * 4)

__global__ void k_attn(const float* __restrict__ Q, const float* __restrict__ Kg,
                       const float* __restrict__ Vg, float* __restrict__ O) {
    extern __shared__ float sm[];
    float* smq = sm + SQ_OFF;
    float* smk = sm + SK_OFF;
    float* smv = sm + SV_OFF;
    float* st  = sm + ST_OFF;
    int h = blockIdx.y;
    int t0 = blockIdx.x * AT;
    int tid = threadIdx.x;

    for (int p0 = tid; p0 < 2048; p0 += 256) {
        int d = p0 >> 5, b = p0 & 31;
        size_t base = ((size_t)(h * 64 + d) * 32 + b) * 2048 + t0;
        float4 a0 = *(const float4*)&Q[base];  float4 a1 = *(const float4*)&Q[base + 4];
        float4 k0 = *(const float4*)&Kg[base]; float4 k1 = *(const float4*)&Kg[base + 4];
        float4 v0 = *(const float4*)&Vg[base]; float4 v1 = *(const float4*)&Vg[base + 4];
        float qa[8] = {a0.x, a0.y, a0.z, a0.w, a1.x, a1.y, a1.z, a1.w};
        float ka[8] = {k0.x, k0.y, k0.z, k0.w, k1.x, k1.y, k1.z, k1.w};
        float va[8] = {v0.x, v0.y, v0.z, v0.w, v1.x, v1.y, v1.z, v1.w};
        #pragma unroll
        for (int s = 0; s < 8; s++) {
            smq[(s * 64 + d) * 32 + b] = qa[s];
            smk[(s * 64 + d) * 32 + b] = ka[s];
            smv[(s * 64 + d) * 36 + b] = va[s];
        }
    }
    __syncthreads();

    const float scale = 0.125f;
    int sb = tid >> 3, sp0 = (tid & 7) * 4;
    for (int ttk = 0; ttk < AT; ttk++) {
        float a0 = 0, a1 = 0, a2 = 0, a3 = 0;
        #pragma unroll
        for (int d = 0; d < 64; d++) {
            float qv = smq[(ttk * 64 + d) * 32 + sb];
            float4 kv = *(const float4*)&smk[(ttk * 64 + d) * 32 + sp0];
            a0 += qv * kv.x; a1 += qv * kv.y; a2 += qv * kv.z; a3 += qv * kv.w;
        }
        st[sb * 33 + sp0 + 0] = a0 * scale;
        st[sb * 33 + sp0 + 1] = a1 * scale;
        st[sb * 33 + sp0 + 2] = a2 * scale;
        st[sb * 33 + sp0 + 3] = a3 * scale;
        __syncthreads();
        if (tid < 32) {
            const float* row = st + tid * 33;
            float mx = -1e30f;
            #pragma unroll
            for (int j = 0; j < 32; j++) mx = fmaxf(mx, row[j]);
            float ev[32]; float sum = 0.0f;
            #pragma unroll
            for (int j = 0; j < 32; j++) { ev[j] = expf(row[j] - mx); sum += ev[j]; }
            float inv = 1.0f / sum;
            #pragma unroll
            for (int j = 0; j < 32; j++) smq[ttk * 1152 + tid * 36 + j] = ev[j] * inv;
        }
        __syncthreads();
    }

    for (int rep = 0; rep < 8; rep++) {
        int o = tid + rep * 256;
        int ob = o >> 6, od = o & 63;
        float outv[8];
        #pragma unroll
        for (int s = 0; s < 8; s++) {
            float acc = 0.0f;
            #pragma unroll
            for (int bp = 0; bp < 32; bp += 4) {
                float4 pv = *(const float4*)&smq[s * 1152 + ob * 36 + bp];
                float4 vv = *(const float4*)&smv[(s * 64 + od) * 36 + bp];
                acc += pv.x * vv.x + pv.y * vv.y + pv.z * vv.z + pv.w * vv.w;
            }
            outv[s] = acc;
        }
        size_t base = ((size_t)(h * 64 + od) * 32 + ob) * 2048 + t0;
        float4 w0 = {outv[0], outv[1], outv[2], outv[3]};
        float4 w1 = {outv[4], outv[5], outv[6], outv[7]};
        *(float4*)&O[base] = w0;
        *(float4*)&O[base + 4] = w1;
    }
}

// ---------------- per-t LN stats ----------------
__global__ void k_tstats(const float* __restrict__ X) {
    int t = blockIdx.x * 32 + threadIdx.x;
    int ry = blockIdx.y;
    double s = 0, q = 0;
    for (int r = ry * 2048 + threadIdx.y; r < (ry + 1) * 2048; r += 8) {
        float v = X[(size_t)r * TT + t];
        s += v; q += (double)v * v;
    }
    __shared__ double ss[8][32], qq[8][32];
    ss[threadIdx.y][threadIdx.x] = s;
    qq[threadIdx.y][threadIdx.x] = q;
    __syncthreads();
    if (threadIdx.y == 0) {
        double S = 0, Qq = 0;
        #pragma unroll
        for (int j = 0; j < 8; j++) { S += ss[j][threadIdx.x]; Qq += qq[j][threadIdx.x]; }
        g_tpart[(t * 8 + ry) * 2] = S;
        g_tpart[(t * 8 + ry) * 2 + 1] = Qq;
    }
}

__global__ void k_tfinal() {
    int t = blockIdx.x * 256 + threadIdx.x;
    double s = 0, q = 0;
    for (int i = 0; i < 8; i++) { s += g_tpart[(t * 8 + i) * 2]; q += g_tpart[(t * 8 + i) * 2 + 1]; }
    double n = 16384.0;
    double mu = s / n;
    double var = q / n - mu * mu;
    g_tmean[t] = (float)mu;
    g_trstd[t] = (float)(1.0 / sqrt(var + (double)EPS));
}

// ---------------- output transpose ----------------
__global__ void k_transpose_out(const float* __restrict__ X, float* __restrict__ out) {
    __shared__ float tile[32][33];
    int b = blockIdx.z;
    int t0 = blockIdx.x * 32, f0 = blockIdx.y * 32;
    int tx = threadIdx.x, ty = threadIdx.y;
    #pragma unroll
    for (int i = ty; i < 32; i += 8)
        tile[i][tx] = X[((size_t)(f0 + i) * BB + b) * TT + t0 + tx];
    __syncthreads();
    #pragma unroll
    for (int i = ty; i < 32; i += 8)
        out[((size_t)b * TT + t0 + i) * CC + f0 + tx] = tile[tx][i];
}

// ---------------- launch --------------------------------------------------
extern "C" void kernel_launch(void* const* d_in, const int* in_sizes, int n_in,
                              void* d_out, int out_size) {
    const float* x     = (const float*)d_in[0];
    const float* dw1_w = (const float*)d_in[1];
    const float* dw1_b = (const float*)d_in[2];
    const float* pw1_w = (const float*)d_in[3];
    const float* pw1_b = (const float*)d_in[4];
    const float* dw2_w = (const float*)d_in[5];
    const float* dw2_b = (const float*)d_in[6];
    const float* pw2_w = (const float*)d_in[7];
    const float* pw2_b = (const float*)d_in[8];
    const float* wq = (const float*)d_in[9];
    const float* bq = (const float*)d_in[10];
    const float* wk = (const float*)d_in[11];
    const float* bk = (const float*)d_in[12];
    const float* wv = (const float*)d_in[13];
    const float* bv = (const float*)d_in[14];
    const float* wp = (const float*)d_in[15];
    const float* bp = (const float*)d_in[16];
    const float* ff_w = (const float*)d_in[17];
    const float* ff_b = (const float*)d_in[18];
    float* out = (float*)d_out;

    float *pX, *pD, *pQ, *pK, *pV;
    __half *pBt, *pWb, *pWb2;
    cudaGetSymbolAddress((void**)&pX, gX);
    cudaGetSymbolAddress((void**)&pD, gD);
    cudaGetSymbolAddress((void**)&pQ, gQ);
    cudaGetSymbolAddress((void**)&pK, gK);
    cudaGetSymbolAddress((void**)&pV, gV);
    cudaGetSymbolAddress((void**)&pBt, gBt);
    cudaGetSymbolAddress((void**)&pWb, gWb);
    cudaGetSymbolAddress((void**)&pWb2, gWb2);

    cudaFuncSetAttribute(k_attn, cudaFuncAttributeMaxDynamicSharedMemorySize, ATTN_SMEM_BYTES);
    cudaFuncSetAttribute(k_mma<0>, cudaFuncAttributeMaxDynamicSharedMemorySize, MMA_SMEM);
    cudaFuncSetAttribute(k_mma<1>, cudaFuncAttributeMaxDynamicSharedMemorySize, MMA_SMEM);

    dim3 cvtG(NN / 32, CC / 32), cvtB32(32, 8);
    dim3 mmaG(4, 512);   // m fast -> B tiles shared across m in L2

    // 0) input transpose + positional encoding
    k_transpose_in<<<dim3(TT / 32, CC / 32, BB), dim3(32, 8)>>>(x, pX);

    // 1) conv block 1: X = pw1 @ dwconv1(LN_b(X)) + b
    k_bstats<<<dim3(32, 32), 256>>>(pX);
    k_bfinal<<<1, 32>>>();
    k_dwconv<<<dim3(CC, BB), 256>>>(pX, dw1_w, dw1_b, pD);
    k_cvtB<0><<<cvtG, cvtB32>>>(pD, pBt);
    k_cvtW<<<1024, 256>>>(pw1_w, pWb);
    k_mma<0><<<mmaG, 256, MMA_SMEM>>>(pWb, pBt, pw1_b, pX);

    // 2) conv blocks 2..4 (shared weights): X += pw2 @ dwconv2(LN_b(X)) + b
    k_cvtW<<<1024, 256>>>(pw2_w, pWb2);
    for (int it = 0; it < 3; it++) {
        k_bstats<<<dim3(32, 32), 256>>>(pX);
        k_bfinal<<<1, 32>>>();
        k_dwconv<<<dim3(CC, BB), 256>>>(pX, dw2_w, dw2_b, pD);
        k_cvtB<0><<<cvtG, cvtB32>>>(pD, pBt);
        k_mma<1><<<mmaG, 256, MMA_SMEM>>>(pWb2, pBt, pw2_b, pX);
    }

    // 3) attention over batch axis
    k_bstats<<<dim3(32, 32), 256>>>(pX);
    k_bfinal<<<1, 32>>>();
    k_cvtB<1><<<cvtG, cvtB32>>>(pX, pBt);    // Y = LN_b(X), fused into convert
    k_cvtW<<<1024, 256>>>(wq, pWb);
    k_mma<0><<<mmaG, 256, MMA_SMEM>>>(pWb, pBt, bq, pQ);
    k_cvtW<<<1024, 256>>>(wk, pWb);
    k_mma<0><<<mmaG, 256, MMA_SMEM>>>(pWb, pBt, bk, pK);
    k_cvtW<<<1024, 256>>>(wv, pWb);
    k_mma<0><<<mmaG, 256, MMA_SMEM>>>(pWb, pBt, bv, pV);
    k_attn<<<dim3(TT / AT, HH), 256, ATTN_SMEM_BYTES>>>(pQ, pK, pV, pD);
    k_cvtB<0><<<cvtG, cvtB32>>>(pD, pBt);
    k_cvtW<<<1024, 256>>>(wp, pWb);
    k_mma<1><<<mmaG, 256, MMA_SMEM>>>(pWb, pBt, bp, pX);

    // 4) FF with per-t LN: X += ff_w @ LN_t(X) + ff_b
    k_tstats<<<dim3(TT / 32, 8), dim3(32, 8)>>>(pX);
    k_tfinal<<<TT / 256, 256>>>();
    k_cvtB<2><<<cvtG, cvtB32>>>(pX, pBt);    // Y = LN_t(X), fused into convert
    k_cvtW<<<1024, 256>>>(ff_w, pWb);
    k_mma<1><<<mmaG, 256, MMA_SMEM>>>(pWb, pBt, ff_b, pX);

    // 5) output transpose
    k_transpose_out<<<dim3(TT / 32, CC / 32, BB), dim3(32, 8)>>>(pX, out);

    (void)in_sizes; (void)n_in; (void)out_size;
}

// round 5
// speedup vs baseline: 2.6589x; 1.3405x over previous
#include <cuda_runtime.h>
#include <cuda_fp16.h>
#include <cstdint>
#include <math.h>

// ---------------- problem constants ----------------
#define BB 32
#define TT 2048
#define CC 512          // E == F == 512
#define NN 65536        // B*T
#define HH 8
#define EPS 1e-5

// ---------------- scratch (device globals; allocation-free rule) ----------
__device__ float gX[33554432];   // state, layout (C, B, T) fp32
__device__ float gQ[33554432];
__device__ float gK[33554432];
__device__ float gV[33554432];
__device__ __half gBt[33554432]; // GEMM B operand, K-major [512][65536] fp16
__device__ __half gWb[262144];   // W operand fp16 [512][512]
__device__ __half gWb2[262144];  // pw2 weights (converted once)

__device__ double g_bpart[32 * 32 * 2];      // per-batch partial (sum, sumsq)
__device__ float  g_bmean[32], g_brstd[32];
__device__ double g_tpart[2048 * 8 * 2];     // per-t partial (sum, sumsq)
__device__ float  g_tmean[2048], g_trstd[2048];

// ================= helpers =================
__device__ __forceinline__ uint32_t smem_u32(const void* p) {
    uint32_t a;
    asm("{ .reg .u64 t; cvta.to.shared.u64 t, %1; cvt.u32.u64 %0, t; }" : "=r"(a) : "l"(p));
    return a;
}
__device__ __forceinline__ void cp_async16(uint32_t smaddr, const void* g) {
    asm volatile("cp.async.cg.shared.global [%0], [%1], 16;" :: "r"(smaddr), "l"(g));
}
#define CP_COMMIT() asm volatile("cp.async.commit_group;" ::: "memory")
#define CP_WAIT1()  asm volatile("cp.async.wait_group 1;" ::: "memory")

__device__ __forceinline__ void ldmatrix_x4(uint32_t& r0, uint32_t& r1, uint32_t& r2,
                                            uint32_t& r3, uint32_t addr) {
    asm volatile("ldmatrix.sync.aligned.m8n8.x4.shared.b16 {%0,%1,%2,%3}, [%4];"
        : "=r"(r0), "=r"(r1), "=r"(r2), "=r"(r3) : "r"(addr));
}
__device__ __forceinline__ void ldmatrix_x4_trans(uint32_t& r0, uint32_t& r1, uint32_t& r2,
                                                  uint32_t& r3, uint32_t addr) {
    asm volatile("ldmatrix.sync.aligned.m8n8.x4.trans.shared.b16 {%0,%1,%2,%3}, [%4];"
        : "=r"(r0), "=r"(r1), "=r"(r2), "=r"(r3) : "r"(addr));
}
__device__ __forceinline__ void mma16816(float* d, const uint32_t* a, uint32_t b0, uint32_t b1) {
    asm volatile(
        "mma.sync.aligned.m16n8k16.row.col.f32.f16.f16.f32 "
        "{%0,%1,%2,%3}, {%4,%5,%6,%7}, {%8,%9}, {%0,%1,%2,%3};"
        : "+f"(d[0]), "+f"(d[1]), "+f"(d[2]), "+f"(d[3])
        : "r"(a[0]), "r"(a[1]), "r"(a[2]), "r"(a[3]), "r"(b0), "r"(b1));
}

// ---------------- input transpose + positional encoding -------------------
__global__ void k_transpose_in(const float* __restrict__ in, float* __restrict__ X) {
    __shared__ float tile[32][33];
    int b = blockIdx.z;
    int t0 = blockIdx.x * 32, c0 = blockIdx.y * 32;
    int tx = threadIdx.x, ty = threadIdx.y;
    #pragma unroll
    for (int i = ty; i < 32; i += 8)
        tile[i][tx] = in[((size_t)b * TT + t0 + i) * CC + c0 + tx];
    __syncthreads();
    #pragma unroll
    for (int i = ty; i < 32; i += 8) {
        int c = c0 + i;
        float div = expf((float)(c & ~1) * (-9.210340371976184f / 512.0f));
        float ang = (float)b * div;
        float pe = (c & 1) ? cosf(ang) : sinf(ang);
        X[((size_t)c * BB + b) * TT + t0 + tx] = tile[tx][i] + pe;
    }
}

// ---------------- per-batch LN stats ----------------
__global__ void k_bstats(const float* __restrict__ X) {
    int b = blockIdx.x, cy = blockIdx.y;
    int tid = threadIdx.x;
    double s = 0, q = 0;
    for (int c = cy * 16; c < cy * 16 + 16; c++) {
        const float* row = X + ((size_t)c * BB + b) * TT;
        for (int t = tid; t < TT; t += 256) { float v = row[t]; s += v; q += (double)v * v; }
    }
    __shared__ double ss[256], qq[256];
    ss[tid] = s; qq[tid] = q; __syncthreads();
    for (int o = 128; o > 0; o >>= 1) {
        if (tid < o) { ss[tid] += ss[tid + o]; qq[tid] += qq[tid + o]; }
        __syncthreads();
    }
    if (tid == 0) {
        g_bpart[(b * 32 + cy) * 2] = ss[0];
        g_bpart[(b * 32 + cy) * 2 + 1] = qq[0];
    }
}

__global__ void k_bfinal() {
    int b = threadIdx.x;
    if (b < 32) {
        double s = 0, q = 0;
        for (int i = 0; i < 32; i++) { s += g_bpart[(b * 32 + i) * 2]; q += g_bpart[(b * 32 + i) * 2 + 1]; }
        double n = 1048576.0;
        double mu = s / n;
        double var = q / n - mu * mu;
        g_bmean[b] = (float)mu;
        g_brstd[b] = (float)(1.0 / sqrt(var + (double)EPS));
    }
}

// ---------------- fused per-batch-LN + depthwise conv (k=7) -> fp16 B operand
__global__ void k_dwconv(const float* __restrict__ X, const float* __restrict__ dww,
                         const float* __restrict__ dwb, __half* __restrict__ D) {
    int c = blockIdx.x, b = blockIdx.y;
    int tid = threadIdx.x;
    __shared__ float s[TT + 8];
    float mu = g_bmean[b], r = g_brstd[b];
    const float* row = X + ((size_t)c * BB + b) * TT;
    for (int t = tid; t < TT; t += 256) s[t + 3] = (row[t] - mu) * r;
    if (tid < 3) { s[tid] = 0.0f; s[TT + 3 + tid] = 0.0f; }
    __syncthreads();
    float w0 = dww[c * 7 + 0], w1 = dww[c * 7 + 1], w2 = dww[c * 7 + 2], w3 = dww[c * 7 + 3];
    float w4 = dww[c * 7 + 4], w5 = dww[c * 7 + 5], w6 = dww[c * 7 + 6];
    float bias = dwb[c];
    __half* drow = D + ((size_t)c * BB + b) * TT;
    for (int t = tid; t < TT; t += 256) {
        float acc = bias;
        acc += w0 * s[t + 0]; acc += w1 * s[t + 1]; acc += w2 * s[t + 2];
        acc += w3 * s[t + 3]; acc += w4 * s[t + 4]; acc += w5 * s[t + 5];
        acc += w6 * s[t + 6];
        drow[t] = __float2half_rn(acc);
    }
}

// ---------------- elementwise LN + fp32->fp16 (layout preserved, K-major) ---
// MODE 1: per-batch LN; MODE 2: per-t LN
template <int MODE>
__global__ void k_cvtBe(const float* __restrict__ X, __half* __restrict__ Bt) {
    size_t i = ((size_t)blockIdx.x * 256 + threadIdx.x) * 4;
    float4 v = *(const float4*)&X[i];
    if (MODE == 1) {
        int b = (int)((i >> 11) & 31);
        float mu = g_bmean[b], sc = g_brstd[b];
        v.x = (v.x - mu) * sc; v.y = (v.y - mu) * sc;
        v.z = (v.z - mu) * sc; v.w = (v.w - mu) * sc;
    } else {
        int t0 = (int)(i & (TT - 1));
        float4 m = *(const float4*)&g_tmean[t0];
        float4 r = *(const float4*)&g_trstd[t0];
        v.x = (v.x - m.x) * r.x; v.y = (v.y - m.y) * r.y;
        v.z = (v.z - m.z) * r.z; v.w = (v.w - m.w) * r.w;
    }
    __half2 h0 = __halves2half2(__float2half_rn(v.x), __float2half_rn(v.y));
    __half2 h1 = __halves2half2(__float2half_rn(v.z), __float2half_rn(v.w));
    uint2 w = { *(uint32_t*)&h0, *(uint32_t*)&h1 };
    *(uint2*)&Bt[i] = w;
}

// ---------------- W convert: fp32 [512][512] -> fp16 [512][512] -----------
__global__ void k_cvtW(const float* __restrict__ W, __half* __restrict__ Wb) {
    int idx = blockIdx.x * 256 + threadIdx.x;
    Wb[idx] = __float2half_rn(W[idx]);
}

// ---------------- tensor-core GEMM: C[512,65536] (+)= W @ X + bias ----------
// A = Wb fp16 [512][512] row-major; B = Bt fp16 [512][65536] K-major.
// mma.sync m16n8k16. CTA 128x128, 8 warps (warp 64x32), K chunks of 64,
// 3-stage cp.async pipeline. B fragments via ldmatrix.trans.
#define KSTAGE 64
#define NSTG 3
#define A_BYTES 16384           // 128 m-rows x 128 B
#define STG_BYTES 32768         // A(16KB) + B(16KB: 64 k-rows x 256 B)
#define MMA_SMEM (NSTG * STG_BYTES)
#define NKC 8

template <int BETA, typename OutT>
__global__ void __launch_bounds__(256, 2)
k_mma(const __half* __restrict__ Wb, const __half* __restrict__ Bt,
      const float* __restrict__ bias, OutT* __restrict__ C, const float* __restrict__ Cin) {
    extern __shared__ char dsm[];
    uint32_t smb = smem_u32(dsm);
    int tid = threadIdx.x;
    int wid = tid >> 5, lane = tid & 31;
    int m0 = blockIdx.x * 128, n0 = blockIdx.y * 128;
    int warp_m = wid >> 2, warp_n = wid & 3;   // 2 x 4 warps, warp tile 64x32

    float acc[4][4][4];
    #pragma unroll
    for (int a = 0; a < 4; a++)
        #pragma unroll
        for (int b = 0; b < 4; b++)
            #pragma unroll
            for (int c = 0; c < 4; c++) acc[a][b][c] = 0.0f;

    int arow = tid >> 3, ach = tid & 7;      // A loads: 32 rows x 8 chunks
    int brow = tid >> 4, bch = tid & 15;     // B loads: 16 rows x 16 chunks

    auto prefetch = [&](int st, int kc) {
        uint32_t sA = smb + st * STG_BYTES;
        uint32_t sB = sA + A_BYTES;
        #pragma unroll
        for (int i = 0; i < 4; i++) {
            int row = arow + i * 32;
            const __half* g = Wb + (size_t)(m0 + row) * 512 + kc * KSTAGE + ach * 8;
            cp_async16(sA + row * 128 + ((ach ^ (row & 7)) << 4), g);
        }
        #pragma unroll
        for (int i = 0; i < 4; i++) {
            int row = brow + i * 16;
            const __half* g = Bt + (size_t)(kc * KSTAGE + row) * NN + n0 + bch * 8;
            cp_async16(sB + row * 256 + ((bch ^ (row & 7)) << 4), g);
        }
    };

    prefetch(0, 0); CP_COMMIT();
    prefetch(1, 1); CP_COMMIT();

    int lr = lane & 7, lq = lane >> 3;
    int rowoff = lr + (lq & 1) * 8;
    int csel = lq >> 1;
    // B trans-load indices
    int bk_off = (lq & 1) * 8 + lr;          // k within k16
    int bn_half = lq >> 1;                   // 0/1 -> n8 sub-block

    for (int i = 0; i < NKC; i++) {
        CP_WAIT1();
        __syncthreads();
        if (i + 2 < NKC) prefetch((i + 2) % NSTG, i + 2);
        CP_COMMIT();

        uint32_t sA = smb + (i % NSTG) * STG_BYTES;
        uint32_t sB = sA + A_BYTES;
        #pragma unroll
        for (int kk = 0; kk < 4; kk++) {
            // B fragments: two x4.trans loads cover n32 x k16
            uint32_t bf[2][4];
            #pragma unroll
            for (int nf = 0; nf < 2; nf++) {
                int krow = kk * 16 + bk_off;
                int nch = warp_n * 4 + nf * 2 + bn_half;
                ldmatrix_x4_trans(bf[nf][0], bf[nf][1], bf[nf][2], bf[nf][3],
                                  sB + krow * 256 + ((nch ^ (krow & 7)) << 4));
            }
            // A fragments
            int chnk = kk * 2 + csel;
            uint32_t af[4][4];
            #pragma unroll
            for (int mf = 0; mf < 4; mf++) {
                int row = warp_m * 64 + mf * 16 + rowoff;
                ldmatrix_x4(af[mf][0], af[mf][1], af[mf][2], af[mf][3],
                            sA + row * 128 + ((chnk ^ (row & 7)) << 4));
            }
            #pragma unroll
            for (int mf = 0; mf < 4; mf++)
                #pragma unroll
                for (int t = 0; t < 4; t++)
                    mma16816(acc[mf][t], af[mf], bf[t >> 1][(t & 1) * 2], bf[t >> 1][(t & 1) * 2 + 1]);
        }
        __syncthreads();
    }

    // epilogue: fused bias (+ residual); OutT float (state) or __half (B operand)
    int g = lane >> 2, tg = lane & 3;
    #pragma unroll
    for (int mf = 0; mf < 4; mf++) {
        int mA = m0 + warp_m * 64 + mf * 16 + g;
        int mB2 = mA + 8;
        float bva = bias[mA], bvb = bias[mB2];
        #pragma unroll
        for (int t = 0; t < 4; t++) {
            int n = n0 + warp_n * 32 + t * 8 + tg * 2;
            size_t o0 = (size_t)mA * NN + n;
            size_t o1 = (size_t)mB2 * NN + n;
            float v00 = acc[mf][t][0] + bva, v01 = acc[mf][t][1] + bva;
            float v10 = acc[mf][t][2] + bvb, v11 = acc[mf][t][3] + bvb;
            if (BETA) {
                float2 p0 = *(const float2*)&Cin[o0];
                float2 p1 = *(const float2*)&Cin[o1];
                v00 += p0.x; v01 += p0.y;
                v10 += p1.x; v11 += p1.y;
            }
            if (sizeof(OutT) == 4) {
                float2 w0 = { v00, v01 }, w1 = { v10, v11 };
                *(float2*)&((float*)C)[o0] = w0;
                *(float2*)&((float*)C)[o1] = w1;
            } else {
                __half2 h0 = __halves2half2(__float2half_rn(v00), __float2half_rn(v01));
                __half2 h1 = __halves2half2(__float2half_rn(v10), __float2half_rn(v11));
                *(uint32_t*)&((__half*)C)[o0] = *(uint32_t*)&h0;
                *(uint32_t*)&((__half*)C)[o1] = *(uint32_t*)&h1;
            }
        }
    }
}

// ---------------- attention over the batch axis -> fp16 B operand ----------
#define AT 8
#define SQ_OFF 0
#define SK_OFF 16384
#define SV_OFF 32768
#define ST_OFF 51200
#define ATTN_SMEM_FLOATS (16384 + 16384 + 18432 + 1056)
#define ATTN_SMEM_BYTES (ATTN_SMEM_FLOATS * 4)

__global__ void k_attn(const float* __restrict__ Q, const float* __restrict__ Kg,
                       const float* __restrict__ Vg, __half* __restrict__ O) {
    extern __shared__ float sm[];
    float* smq = sm + SQ_OFF;
    float* smk = sm + SK_OFF;
    float* smv = sm + SV_OFF;
    float* st  = sm + ST_OFF;
    int h = blockIdx.y;
    int t0 = blockIdx.x * AT;
    int tid = threadIdx.x;

    for (int p0 = tid; p0 < 2048; p0 += 256) {
        int d = p0 >> 5, b = p0 & 31;
        size_t base = ((size_t)(h * 64 + d) * 32 + b) * 2048 + t0;
        float4 a0 = *(const float4*)&Q[base];  float4 a1 = *(const float4*)&Q[base + 4];
        float4 k0 = *(const float4*)&Kg[base]; float4 k1 = *(const float4*)&Kg[base + 4];
        float4 v0 = *(const float4*)&Vg[base]; float4 v1 = *(const float4*)&Vg[base + 4];
        float qa[8] = {a0.x, a0.y, a0.z, a0.w, a1.x, a1.y, a1.z, a1.w};
        float ka[8] = {k0.x, k0.y, k0.z, k0.w, k1.x, k1.y, k1.z, k1.w};
        float va[8] = {v0.x, v0.y, v0.z, v0.w, v1.x, v1.y, v1.z, v1.w};
        #pragma unroll
        for (int s = 0; s < 8; s++) {
            smq[(s * 64 + d) * 32 + b] = qa[s];
            smk[(s * 64 + d) * 32 + b] = ka[s];
            smv[(s * 64 + d) * 36 + b] = va[s];
        }
    }
    __syncthreads();

    const float scale = 0.125f;
    int sb = tid >> 3, sp0 = (tid & 7) * 4;
    for (int ttk = 0; ttk < AT; ttk++) {
        float a0 = 0, a1 = 0, a2 = 0, a3 = 0;
        #pragma unroll
        for (int d = 0; d < 64; d++) {
            float qv = smq[(ttk * 64 + d) * 32 + sb];
            float4 kv = *(const float4*)&smk[(ttk * 64 + d) * 32 + sp0];
            a0 += qv * kv.x; a1 += qv * kv.y; a2 += qv * kv.z; a3 += qv * kv.w;
        }
        st[sb * 33 + sp0 + 0] = a0 * scale;
        st[sb * 33 + sp0 + 1] = a1 * scale;
        st[sb * 33 + sp0 + 2] = a2 * scale;
        st[sb * 33 + sp0 + 3] = a3 * scale;
        __syncthreads();
        if (tid < 32) {
            const float* row = st + tid * 33;
            float mx = -1e30f;
            #pragma unroll
            for (int j = 0; j < 32; j++) mx = fmaxf(mx, row[j]);
            float ev[32]; float sum = 0.0f;
            #pragma unroll
            for (int j = 0; j < 32; j++) { ev[j] = expf(row[j] - mx); sum += ev[j]; }
            float inv = 1.0f / sum;
            #pragma unroll
            for (int j = 0; j < 32; j++) smq[ttk * 1152 + tid * 36 + j] = ev[j] * inv;
        }
        __syncthreads();
    }

    for (int rep = 0; rep < 8; rep++) {
        int o = tid + rep * 256;
        int ob = o >> 6, od = o & 63;
        float outv[8];
        #pragma unroll
        for (int s = 0; s < 8; s++) {
            float acc = 0.0f;
            #pragma unroll
            for (int bp = 0; bp < 32; bp += 4) {
                float4 pv = *(const float4*)&smq[s * 1152 + ob * 36 + bp];
                float4 vv = *(const float4*)&smv[(s * 64 + od) * 36 + bp];
                acc += pv.x * vv.x + pv.y * vv.y + pv.z * vv.z + pv.w * vv.w;
            }
            outv[s] = acc;
        }
        size_t base = ((size_t)(h * 64 + od) * 32 + ob) * 2048 + t0;
        __half2 h0 = __halves2half2(__float2half_rn(outv[0]), __float2half_rn(outv[1]));
        __half2 h1 = __halves2half2(__float2half_rn(outv[2]), __float2half_rn(outv[3]));
        __half2 h2 = __halves2half2(__float2half_rn(outv[4]), __float2half_rn(outv[5]));
        __half2 h3 = __halves2half2(__float2half_rn(outv[6]), __float2half_rn(outv[7]));
        uint4 w = { *(uint32_t*)&h0, *(uint32_t*)&h1, *(uint32_t*)&h2, *(uint32_t*)&h3 };
        *(uint4*)&O[base] = w;
    }
}

// ---------------- per-t LN stats ----------------
__global__ void k_tstats(const float* __restrict__ X) {
    int t = blockIdx.x * 32 + threadIdx.x;
    int ry = blockIdx.y;
    double s = 0, q = 0;
    for (int r = ry * 2048 + threadIdx.y; r < (ry + 1) * 2048; r += 8) {
        float v = X[(size_t)r * TT + t];
        s += v; q += (double)v * v;
    }
    __shared__ double ss[8][32], qq[8][32];
    ss[threadIdx.y][threadIdx.x] = s;
    qq[threadIdx.y][threadIdx.x] = q;
    __syncthreads();
    if (threadIdx.y == 0) {
        double S = 0, Qq = 0;
        #pragma unroll
        for (int j = 0; j < 8; j++) { S += ss[j][threadIdx.x]; Qq += qq[j][threadIdx.x]; }
        g_tpart[(t * 8 + ry) * 2] = S;
        g_tpart[(t * 8 + ry) * 2 + 1] = Qq;
    }
}

__global__ void k_tfinal() {
    int t = blockIdx.x * 256 + threadIdx.x;
    double s = 0, q = 0;
    for (int i = 0; i < 8; i++) { s += g_tpart[(t * 8 + i) * 2]; q += g_tpart[(t * 8 + i) * 2 + 1]; }
    double n = 16384.0;
    double mu = s / n;
    double var = q / n - mu * mu;
    g_tmean[t] = (float)mu;
    g_trstd[t] = (float)(1.0 / sqrt(var + (double)EPS));
}

// ---------------- output transpose ----------------
__global__ void k_transpose_out(const float* __restrict__ X, float* __restrict__ out) {
    __shared__ float tile[32][33];
    int b = blockIdx.z;
    int t0 = blockIdx.x * 32, f0 = blockIdx.y * 32;
    int tx = threadIdx.x, ty = threadIdx.y;
    #pragma unroll
    for (int i = ty; i < 32; i += 8)
        tile[i][tx] = X[((size_t)(f0 + i) * BB + b) * TT + t0 + tx];
    __syncthreads();
    #pragma unroll
    for (int i = ty; i < 32; i += 8)
        out[((size_t)b * TT + t0 + i) * CC + f0 + tx] = tile[tx][i];
}

// ---------------- launch --------------------------------------------------
extern "C" void kernel_launch(void* const* d_in, const int* in_sizes, int n_in,
                              void* d_out, int out_size) {
    const float* x     = (const float*)d_in[0];
    const float* dw1_w = (const float*)d_in[1];
    const float* dw1_b = (const float*)d_in[2];
    const float* pw1_w = (const float*)d_in[3];
    const float* pw1_b = (const float*)d_in[4];
    const float* dw2_w = (const float*)d_in[5];
    const float* dw2_b = (const float*)d_in[6];
    const float* pw2_w = (const float*)d_in[7];
    const float* pw2_b = (const float*)d_in[8];
    const float* wq = (const float*)d_in[9];
    const float* bq = (const float*)d_in[10];
    const float* wk = (const float*)d_in[11];
    const float* bk = (const float*)d_in[12];
    const float* wv = (const float*)d_in[13];
    const float* bv = (const float*)d_in[14];
    const float* wp = (const float*)d_in[15];
    const float* bp = (const float*)d_in[16];
    const float* ff_w = (const float*)d_in[17];
    const float* ff_b = (const float*)d_in[18];
    float* out = (float*)d_out;

    float *pX, *pQ, *pK, *pV;
    __half *pBt, *pWb, *pWb2;
    cudaGetSymbolAddress((void**)&pX, gX);
    cudaGetSymbolAddress((void**)&pQ, gQ);
    cudaGetSymbolAddress((void**)&pK, gK);
    cudaGetSymbolAddress((void**)&pV, gV);
    cudaGetSymbolAddress((void**)&pBt, gBt);
    cudaGetSymbolAddress((void**)&pWb, gWb);
    cudaGetSymbolAddress((void**)&pWb2, gWb2);

    cudaFuncSetAttribute(k_attn, cudaFuncAttributeMaxDynamicSharedMemorySize, ATTN_SMEM_BYTES);
    cudaFuncSetAttribute((k_mma<0, float>), cudaFuncAttributeMaxDynamicSharedMemorySize, MMA_SMEM);
    cudaFuncSetAttribute((k_mma<1, float>), cudaFuncAttributeMaxDynamicSharedMemorySize, MMA_SMEM);
    dim3 mmaG(4, 512);   // m fast -> B tiles shared across m in L2

    // 0) input transpose + positional encoding
    k_transpose_in<<<dim3(TT / 32, CC / 32, BB), dim3(32, 8)>>>(x, pX);

    // 1) conv block 1: X = pw1 @ dwconv1(LN_b(X)) + b
    k_bstats<<<dim3(32, 32), 256>>>(pX);
    k_bfinal<<<1, 32>>>();
    k_dwconv<<<dim3(CC, BB), 256>>>(pX, dw1_w, dw1_b, pBt);
    k_cvtW<<<1024, 256>>>(pw1_w, pWb);
    k_mma<0, float><<<mmaG, 256, MMA_SMEM>>>(pWb, pBt, pw1_b, pX, pX);

    // 2) conv blocks 2..4 (shared weights): X += pw2 @ dwconv2(LN_b(X)) + b
    k_cvtW<<<1024, 256>>>(pw2_w, pWb2);
    for (int it = 0; it < 3; it++) {
        k_bstats<<<dim3(32, 32), 256>>>(pX);
        k_bfinal<<<1, 32>>>();
        k_dwconv<<<dim3(CC, BB), 256>>>(pX, dw2_w, dw2_b, pBt);
        k_mma<1, float><<<mmaG, 256, MMA_SMEM>>>(pWb2, pBt, pw2_b, pX, pX);
    }

    // 3) attention over batch axis
    k_bstats<<<dim3(32, 32), 256>>>(pX);
    k_bfinal<<<1, 32>>>();
    k_cvtBe<1><<<32768, 256>>>(pX, pBt);     // Y = LN_b(X), elementwise convert
    k_cvtW<<<1024, 256>>>(wq, pWb);
    k_mma<0, float><<<mmaG, 256, MMA_SMEM>>>(pWb, pBt, bq, pQ, pQ);
    k_cvtW<<<1024, 256>>>(wk, pWb);
    k_mma<0, float><<<mmaG, 256, MMA_SMEM>>>(pWb, pBt, bk, pK, pK);
    k_cvtW<<<1024, 256>>>(wv, pWb);
    k_mma<0, float><<<mmaG, 256, MMA_SMEM>>>(pWb, pBt, bv, pV, pV);
    k_attn<<<dim3(TT / AT, HH), 256, ATTN_SMEM_BYTES>>>(pQ, pK, pV, pBt);
    k_cvtW<<<1024, 256>>>(wp, pWb);
    k_mma<1, float><<<mmaG, 256, MMA_SMEM>>>(pWb, pBt, bp, pX, pX);

    // 4) FF with per-t LN: X += ff_w @ LN_t(X) + ff_b
    k_tstats<<<dim3(TT / 32, 8), dim3(32, 8)>>>(pX);
    k_tfinal<<<TT / 256, 256>>>();
    k_cvtBe<2><<<32768, 256>>>(pX, pBt);     // Y = LN_t(X), elementwise convert
    k_cvtW<<<1024, 256>>>(ff_w, pWb);
    k_mma<1, float><<<mmaG, 256, MMA_SMEM>>>(pWb, pBt, ff_b, pX, pX);

    // 5) output transpose
    k_transpose_out<<<dim3(TT / 32, CC / 32, BB), dim3(32, 8)>>>(pX, out);

    (void)in_sizes; (void)n_in; (void)out_size;
}

// round 6
// speedup vs baseline: 3.2715x; 1.2304x over previous
#include <cuda_runtime.h>
#include <cuda_fp16.h>
#include <cstdint>
#include <math.h>

// ---------------- problem constants ----------------
#define BB 32
#define TT 2048
#define CC 512          // E == F == 512
#define NN 65536        // B*T
#define HH 8
#define EPS 1e-5

// ---------------- scratch (device globals; allocation-free rule) ----------
__device__ float gX[33554432];     // state, layout (C, B, T) fp32
__device__ __half gBt[33554432];   // GEMM B operand, K-major [512][65536] fp16
__device__ __half gQKV[100663296]; // merged QKV output fp16 [1536][65536]
__device__ __half gWb[262144];     // W operand fp16 [512][512]
__device__ __half gWb2[262144];    // pw2 weights (converted once)
__device__ __half gWqkv[786432];   // merged q|k|v weights fp16 [1536][512]
__device__ float gBqkv[1536];      // merged q|k|v bias

__device__ float g_bacc[64];       // per-batch (sum, sumsq) fp32 accumulators
__device__ float g_bmean[32], g_brstd[32];
__device__ float g_tacc[4096];     // per-t (sum, sumsq)
__device__ float g_tmean[2048], g_trstd[2048];

// ================= helpers =================
__device__ __forceinline__ uint32_t smem_u32(const void* p) {
    uint32_t a;
    asm("{ .reg .u64 t; cvta.to.shared.u64 t, %1; cvt.u32.u64 %0, t; }" : "=r"(a) : "l"(p));
    return a;
}
__device__ __forceinline__ void cp_async16(uint32_t smaddr, const void* g) {
    asm volatile("cp.async.cg.shared.global [%0], [%1], 16;" :: "r"(smaddr), "l"(g));
}
#define CP_COMMIT() asm volatile("cp.async.commit_group;" ::: "memory")
#define CP_WAIT1()  asm volatile("cp.async.wait_group 1;" ::: "memory")

__device__ __forceinline__ void ldmatrix_x4(uint32_t& r0, uint32_t& r1, uint32_t& r2,
                                            uint32_t& r3, uint32_t addr) {
    asm volatile("ldmatrix.sync.aligned.m8n8.x4.shared.b16 {%0,%1,%2,%3}, [%4];"
        : "=r"(r0), "=r"(r1), "=r"(r2), "=r"(r3) : "r"(addr));
}
__device__ __forceinline__ void ldmatrix_x4_trans(uint32_t& r0, uint32_t& r1, uint32_t& r2,
                                                  uint32_t& r3, uint32_t addr) {
    asm volatile("ldmatrix.sync.aligned.m8n8.x4.trans.shared.b16 {%0,%1,%2,%3}, [%4];"
        : "=r"(r0), "=r"(r1), "=r"(r2), "=r"(r3) : "r"(addr));
}
__device__ __forceinline__ void mma16816(float* d, const uint32_t* a, uint32_t b0, uint32_t b1) {
    asm volatile(
        "mma.sync.aligned.m16n8k16.row.col.f32.f16.f16.f32 "
        "{%0,%1,%2,%3}, {%4,%5,%6,%7}, {%8,%9}, {%0,%1,%2,%3};"
        : "+f"(d[0]), "+f"(d[1]), "+f"(d[2]), "+f"(d[3])
        : "r"(a[0]), "r"(a[1]), "r"(a[2]), "r"(a[3]), "r"(b0), "r"(b1));
}

// ---------------- zero stat accumulators (start of graph) ------------------
__global__ void k_zeroacc() {
    int i = blockIdx.x * 256 + threadIdx.x;
    if (i < 64) g_bacc[i] = 0.0f;
    if (i < 4096) g_tacc[i] = 0.0f;
}

// ---------------- input transpose + positional encoding + batch stats ------
__global__ void k_transpose_in(const float* __restrict__ in, float* __restrict__ X) {
    __shared__ float tile[32][33];
    __shared__ float rs[256], rq[256];
    int b = blockIdx.z;
    int t0 = blockIdx.x * 32, c0 = blockIdx.y * 32;
    int tx = threadIdx.x, ty = threadIdx.y;
    #pragma unroll
    for (int i = ty; i < 32; i += 8)
        tile[i][tx] = in[((size_t)b * TT + t0 + i) * CC + c0 + tx];
    __syncthreads();
    float s = 0.0f, q = 0.0f;
    #pragma unroll
    for (int i = ty; i < 32; i += 8) {
        int c = c0 + i;
        float div = expf((float)(c & ~1) * (-9.210340371976184f / 512.0f));
        float ang = (float)b * div;
        float pe = (c & 1) ? cosf(ang) : sinf(ang);
        float v = tile[tx][i] + pe;
        X[((size_t)c * BB + b) * TT + t0 + tx] = v;
        s += v; q += v * v;
    }
    int tid = ty * 32 + tx;
    rs[tid] = s; rq[tid] = q;
    __syncthreads();
    for (int o = 128; o > 0; o >>= 1) {
        if (tid < o) { rs[tid] += rs[tid + o]; rq[tid] += rq[tid + o]; }
        __syncthreads();
    }
    if (tid == 0) {
        atomicAdd(&g_bacc[2 * b], rs[0]);
        atomicAdd(&g_bacc[2 * b + 1], rq[0]);
    }
}

// ---------------- finalize per-batch stats (and re-zero accumulators) ------
__global__ void k_bfinal() {
    int b = threadIdx.x;
    if (b < 32) {
        double s = (double)g_bacc[2 * b], q = (double)g_bacc[2 * b + 1];
        double n = 1048576.0;
        double mu = s / n;
        double var = q / n - mu * mu;
        g_bmean[b] = (float)mu;
        g_brstd[b] = (float)(1.0 / sqrt(var + (double)EPS));
        g_bacc[2 * b] = 0.0f;
        g_bacc[2 * b + 1] = 0.0f;
    }
}

// ---------------- finalize per-t stats ----------------
__global__ void k_tfinal() {
    int t = blockIdx.x * 256 + threadIdx.x;
    double s = (double)g_tacc[2 * t], q = (double)g_tacc[2 * t + 1];
    double n = 16384.0;
    double mu = s / n;
    double var = q / n - mu * mu;
    g_tmean[t] = (float)mu;
    g_trstd[t] = (float)(1.0 / sqrt(var + (double)EPS));
    g_tacc[2 * t] = 0.0f;
    g_tacc[2 * t + 1] = 0.0f;
}

// ---------------- fused per-batch-LN + depthwise conv (k=7) -> fp16 --------
__global__ void k_dwconv(const float* __restrict__ X, const float* __restrict__ dww,
                         const float* __restrict__ dwb, __half* __restrict__ D) {
    int c = blockIdx.x, b = blockIdx.y;
    int tid = threadIdx.x;
    __shared__ float s[TT + 8];
    float mu = g_bmean[b], r = g_brstd[b];
    const float* row = X + ((size_t)c * BB + b) * TT;
    for (int t = tid; t < TT; t += 256) s[t + 3] = (row[t] - mu) * r;
    if (tid < 3) { s[tid] = 0.0f; s[TT + 3 + tid] = 0.0f; }
    __syncthreads();
    float w0 = dww[c * 7 + 0], w1 = dww[c * 7 + 1], w2 = dww[c * 7 + 2], w3 = dww[c * 7 + 3];
    float w4 = dww[c * 7 + 4], w5 = dww[c * 7 + 5], w6 = dww[c * 7 + 6];
    float bias = dwb[c];
    __half* drow = D + ((size_t)c * BB + b) * TT;
    for (int t = tid; t < TT; t += 256) {
        float acc = bias;
        acc += w0 * s[t + 0]; acc += w1 * s[t + 1]; acc += w2 * s[t + 2];
        acc += w3 * s[t + 3]; acc += w4 * s[t + 4]; acc += w5 * s[t + 5];
        acc += w6 * s[t + 6];
        drow[t] = __float2half_rn(acc);
    }
}

// ---------------- elementwise LN + fp32->fp16 (layout preserved) -----------
// MODE 1: per-batch LN; MODE 2: per-t LN
template <int MODE>
__global__ void k_cvtBe(const float* __restrict__ X, __half* __restrict__ Bt) {
    size_t i = ((size_t)blockIdx.x * 256 + threadIdx.x) * 4;
    float4 v = *(const float4*)&X[i];
    if (MODE == 1) {
        int b = (int)((i >> 11) & 31);
        float mu = g_bmean[b], sc = g_brstd[b];
        v.x = (v.x - mu) * sc; v.y = (v.y - mu) * sc;
        v.z = (v.z - mu) * sc; v.w = (v.w - mu) * sc;
    } else {
        int t0 = (int)(i & (TT - 1));
        float4 m = *(const float4*)&g_tmean[t0];
        float4 r = *(const float4*)&g_trstd[t0];
        v.x = (v.x - m.x) * r.x; v.y = (v.y - m.y) * r.y;
        v.z = (v.z - m.z) * r.z; v.w = (v.w - m.w) * r.w;
    }
    __half2 h0 = __halves2half2(__float2half_rn(v.x), __float2half_rn(v.y));
    __half2 h1 = __halves2half2(__float2half_rn(v.z), __float2half_rn(v.w));
    uint2 w = { *(uint32_t*)&h0, *(uint32_t*)&h1 };
    *(uint2*)&Bt[i] = w;
}

// ---------------- W convert: fp32 [512][512] -> fp16 -----------------------
__global__ void k_cvtW(const float* __restrict__ W, __half* __restrict__ Wb) {
    int idx = blockIdx.x * 256 + threadIdx.x;
    Wb[idx] = __float2half_rn(W[idx]);
}

// ---------------- pack merged q|k|v weights + bias --------------------------
__global__ void k_packqkv(const float* __restrict__ wq, const float* __restrict__ wk,
                          const float* __restrict__ wv, const float* __restrict__ bq,
                          const float* __restrict__ bk, const float* __restrict__ bv,
                          __half* __restrict__ W, float* __restrict__ B) {
    int idx = blockIdx.x * 256 + threadIdx.x;   // 0..786431
    int sel = idx >> 18;
    int off = idx & 262143;
    const float* src = (sel == 0) ? wq : ((sel == 1) ? wk : wv);
    W[idx] = __float2half_rn(src[off]);
    if (off < 512) {
        const float* bs = (sel == 0) ? bq : ((sel == 1) ? bk : bv);
        B[sel * 512 + off] = bs[off];
    }
}

// ---------------- tensor-core GEMM: C[M,65536] (+)= W @ X + bias ------------
// A fp16 [M][512] row-major; B fp16 [512][65536] K-major.
// CTA 128x128, 8 warps (64x32), K chunks of 64, 3-stage cp.async.
// STATS: 0 none, 1 per-batch (sum,sumsq) of outputs, 2 per-t.
// TRANS: write output transposed to (n, m) layout (final out tensor).
#define KSTAGE 64
#define NSTG 3
#define A_BYTES 16384
#define STG_BYTES 32768
#define MMA_SMEM (NSTG * STG_BYTES)
#define NKC 8

template <int BETA, int STATS, int TRANS, typename OutT>
__global__ void __launch_bounds__(256, 2)
k_mma(const __half* __restrict__ Wb, const __half* __restrict__ Bt,
      const float* __restrict__ bias, OutT* __restrict__ C, const float* __restrict__ Cin) {
    extern __shared__ char dsm[];
    uint32_t smb = smem_u32(dsm);
    int tid = threadIdx.x;
    int wid = tid >> 5, lane = tid & 31;
    int m0 = blockIdx.x * 128, n0 = blockIdx.y * 128;
    int warp_m = wid >> 2, warp_n = wid & 3;

    float acc[4][4][4];
    #pragma unroll
    for (int a = 0; a < 4; a++)
        #pragma unroll
        for (int b = 0; b < 4; b++)
            #pragma unroll
            for (int c = 0; c < 4; c++) acc[a][b][c] = 0.0f;

    int arow = tid >> 3, ach = tid & 7;
    int brow = tid >> 4, bch = tid & 15;

    auto prefetch = [&](int st, int kc) {
        uint32_t sA = smb + st * STG_BYTES;
        uint32_t sB = sA + A_BYTES;
        #pragma unroll
        for (int i = 0; i < 4; i++) {
            int row = arow + i * 32;
            const __half* g = Wb + (size_t)(m0 + row) * 512 + kc * KSTAGE + ach * 8;
            cp_async16(sA + row * 128 + ((ach ^ (row & 7)) << 4), g);
        }
        #pragma unroll
        for (int i = 0; i < 4; i++) {
            int row = brow + i * 16;
            const __half* g = Bt + (size_t)(kc * KSTAGE + row) * NN + n0 + bch * 8;
            cp_async16(sB + row * 256 + ((bch ^ (row & 7)) << 4), g);
        }
    };

    prefetch(0, 0); CP_COMMIT();
    prefetch(1, 1); CP_COMMIT();

    int lr = lane & 7, lq = lane >> 3;
    int rowoff = lr + (lq & 1) * 8;
    int csel = lq >> 1;
    int bk_off = (lq & 1) * 8 + lr;
    int bn_half = lq >> 1;

    for (int i = 0; i < NKC; i++) {
        CP_WAIT1();
        __syncthreads();
        if (i + 2 < NKC) prefetch((i + 2) % NSTG, i + 2);
        CP_COMMIT();

        uint32_t sA = smb + (i % NSTG) * STG_BYTES;
        uint32_t sB = sA + A_BYTES;
        #pragma unroll
        for (int kk = 0; kk < 4; kk++) {
            uint32_t bf[2][4];
            #pragma unroll
            for (int nf = 0; nf < 2; nf++) {
                int krow = kk * 16 + bk_off;
                int nch = warp_n * 4 + nf * 2 + bn_half;
                ldmatrix_x4_trans(bf[nf][0], bf[nf][1], bf[nf][2], bf[nf][3],
                                  sB + krow * 256 + ((nch ^ (krow & 7)) << 4));
            }
            int chnk = kk * 2 + csel;
            uint32_t af[4][4];
            #pragma unroll
            for (int mf = 0; mf < 4; mf++) {
                int row = warp_m * 64 + mf * 16 + rowoff;
                ldmatrix_x4(af[mf][0], af[mf][1], af[mf][2], af[mf][3],
                            sA + row * 128 + ((chnk ^ (row & 7)) << 4));
            }
            #pragma unroll
            for (int mf = 0; mf < 4; mf++)
                #pragma unroll
                for (int t = 0; t < 4; t++)
                    mma16816(acc[mf][t], af[mf], bf[t >> 1][(t & 1) * 2], bf[t >> 1][(t & 1) * 2 + 1]);
        }
        __syncthreads();
    }

    // ---- epilogue ----
    float* colsum = (float*)dsm;        // STATS==2: [128] + [128]
    float* colsq  = colsum + 128;
    float* stg    = (float*)dsm;        // TRANS: [128][132]
    if (STATS == 2) {
        if (tid < 128) { colsum[tid] = 0.0f; colsq[tid] = 0.0f; }
        __syncthreads();
    }
    float s_part = 0.0f, q_part = 0.0f;
    int g = lane >> 2, tg = lane & 3;
    #pragma unroll
    for (int mf = 0; mf < 4; mf++) {
        int mlA = warp_m * 64 + mf * 16 + g;
        int mlB = mlA + 8;
        int mA = m0 + mlA, mB2 = m0 + mlB;
        float bva = bias[mA], bvb = bias[mB2];
        #pragma unroll
        for (int t = 0; t < 4; t++) {
            int nl = warp_n * 32 + t * 8 + tg * 2;
            int n = n0 + nl;
            size_t o0 = (size_t)mA * NN + n;
            size_t o1 = (size_t)mB2 * NN + n;
            float v00 = acc[mf][t][0] + bva, v01 = acc[mf][t][1] + bva;
            float v10 = acc[mf][t][2] + bvb, v11 = acc[mf][t][3] + bvb;
            if (BETA) {
                float2 p0 = *(const float2*)&Cin[o0];
                float2 p1 = *(const float2*)&Cin[o1];
                v00 += p0.x; v01 += p0.y;
                v10 += p1.x; v11 += p1.y;
            }
            if (STATS == 1) {
                s_part += v00 + v01 + v10 + v11;
                q_part += v00 * v00 + v01 * v01 + v10 * v10 + v11 * v11;
            }
            if (STATS == 2) {
                atomicAdd(&colsum[nl], v00 + v10);
                atomicAdd(&colsum[nl + 1], v01 + v11);
                atomicAdd(&colsq[nl], v00 * v00 + v10 * v10);
                atomicAdd(&colsq[nl + 1], v01 * v01 + v11 * v11);
            }
            if (TRANS) {
                stg[nl * 132 + mlA] = v00;
                stg[(nl + 1) * 132 + mlA] = v01;
                stg[nl * 132 + mlB] = v10;
                stg[(nl + 1) * 132 + mlB] = v11;
            } else if (sizeof(OutT) == 4) {
                float2 w0 = { v00, v01 }, w1 = { v10, v11 };
                *(float2*)&((float*)C)[o0] = w0;
                *(float2*)&((float*)C)[o1] = w1;
            } else {
                __half2 h0 = __halves2half2(__float2half_rn(v00), __float2half_rn(v01));
                __half2 h1 = __halves2half2(__float2half_rn(v10), __float2half_rn(v11));
                *(uint32_t*)&((__half*)C)[o0] = *(uint32_t*)&h0;
                *(uint32_t*)&((__half*)C)[o1] = *(uint32_t*)&h1;
            }
        }
    }
    if (STATS == 1) {
        float* red = (float*)dsm;
        red[tid] = s_part; red[256 + tid] = q_part;
        __syncthreads();
        for (int o = 128; o > 0; o >>= 1) {
            if (tid < o) { red[tid] += red[tid + o]; red[256 + tid] += red[256 + tid + o]; }
            __syncthreads();
        }
        if (tid == 0) {
            int b = n0 >> 11;
            atomicAdd(&g_bacc[2 * b], red[0]);
            atomicAdd(&g_bacc[2 * b + 1], red[256]);
        }
    }
    if (STATS == 2) {
        __syncthreads();
        if (tid < 128) {
            int t = (n0 + tid) & (TT - 1);
            atomicAdd(&g_tacc[2 * t], colsum[tid]);
            atomicAdd(&g_tacc[2 * t + 1], colsq[tid]);
        }
    }
    if (TRANS) {
        __syncthreads();
        int ml = tid & 127;
        for (int nl = tid >> 7; nl < 128; nl += 2)
            ((float*)C)[(size_t)(n0 + nl) * CC + m0 + ml] = stg[nl * 132 + ml];
    }
}

// ---------------- attention over the batch axis (fp16 QKV in, fp16 out) ----
#define AT 8
#define SQ_OFF 0
#define SK_OFF 16384
#define SV_OFF 32768
#define ST_OFF 51200
#define ATTN_SMEM_FLOATS (16384 + 16384 + 18432 + 1056)
#define ATTN_SMEM_BYTES (ATTN_SMEM_FLOATS * 4)

__global__ void k_attn(const __half* __restrict__ QKV, __half* __restrict__ O) {
    extern __shared__ float sm[];
    float* smq = sm + SQ_OFF;
    float* smk = sm + SK_OFF;
    float* smv = sm + SV_OFF;
    float* st  = sm + ST_OFF;
    int h = blockIdx.y;
    int t0 = blockIdx.x * AT;
    int tid = threadIdx.x;

    const __half* Qh = QKV;
    const __half* Kh = QKV + (size_t)512 * NN;
    const __half* Vh = QKV + (size_t)1024 * NN;

    for (int p0 = tid; p0 < 2048; p0 += 256) {
        int d = p0 >> 5, b = p0 & 31;
        size_t base = ((size_t)(h * 64 + d) * 32 + b) * 2048 + t0;
        uint4 qr = *(const uint4*)&Qh[base];
        uint4 kr = *(const uint4*)&Kh[base];
        uint4 vr = *(const uint4*)&Vh[base];
        __half2* qh = (__half2*)&qr;
        __half2* kh = (__half2*)&kr;
        __half2* vh = (__half2*)&vr;
        #pragma unroll
        for (int j = 0; j < 4; j++) {
            float2 qf = __half22float2(qh[j]);
            float2 kf = __half22float2(kh[j]);
            float2 vf = __half22float2(vh[j]);
            smq[((2 * j) * 64 + d) * 32 + b] = qf.x;
            smq[((2 * j + 1) * 64 + d) * 32 + b] = qf.y;
            smk[((2 * j) * 64 + d) * 32 + b] = kf.x;
            smk[((2 * j + 1) * 64 + d) * 32 + b] = kf.y;
            smv[((2 * j) * 64 + d) * 36 + b] = vf.x;
            smv[((2 * j + 1) * 64 + d) * 36 + b] = vf.y;
        }
    }
    __syncthreads();

    const float scale = 0.125f;
    int sb = tid >> 3, sp0 = (tid & 7) * 4;
    for (int ttk = 0; ttk < AT; ttk++) {
        float a0 = 0, a1 = 0, a2 = 0, a3 = 0;
        #pragma unroll
        for (int d = 0; d < 64; d++) {
            float qv = smq[(ttk * 64 + d) * 32 + sb];
            float4 kv = *(const float4*)&smk[(ttk * 64 + d) * 32 + sp0];
            a0 += qv * kv.x; a1 += qv * kv.y; a2 += qv * kv.z; a3 += qv * kv.w;
        }
        st[sb * 33 + sp0 + 0] = a0 * scale;
        st[sb * 33 + sp0 + 1] = a1 * scale;
        st[sb * 33 + sp0 + 2] = a2 * scale;
        st[sb * 33 + sp0 + 3] = a3 * scale;
        __syncthreads();
        if (tid < 32) {
            const float* row = st + tid * 33;
            float mx = -1e30f;
            #pragma unroll
            for (int j = 0; j < 32; j++) mx = fmaxf(mx, row[j]);
            float ev[32]; float sum = 0.0f;
            #pragma unroll
            for (int j = 0; j < 32; j++) { ev[j] = expf(row[j] - mx); sum += ev[j]; }
            float inv = 1.0f / sum;
            #pragma unroll
            for (int j = 0; j < 32; j++) smq[ttk * 1152 + tid * 36 + j] = ev[j] * inv;
        }
        __syncthreads();
    }

    for (int rep = 0; rep < 8; rep++) {
        int o = tid + rep * 256;
        int ob = o >> 6, od = o & 63;
        float outv[8];
        #pragma unroll
        for (int s = 0; s < 8; s++) {
            float acc = 0.0f;
            #pragma unroll
            for (int bp = 0; bp < 32; bp += 4) {
                float4 pv = *(const float4*)&smq[s * 1152 + ob * 36 + bp];
                float4 vv = *(const float4*)&smv[(s * 64 + od) * 36 + bp];
                acc += pv.x * vv.x + pv.y * vv.y + pv.z * vv.z + pv.w * vv.w;
            }
            outv[s] = acc;
        }
        size_t base = ((size_t)(h * 64 + od) * 32 + ob) * 2048 + t0;
        __half2 h0 = __halves2half2(__float2half_rn(outv[0]), __float2half_rn(outv[1]));
        __half2 h1 = __halves2half2(__float2half_rn(outv[2]), __float2half_rn(outv[3]));
        __half2 h2 = __halves2half2(__float2half_rn(outv[4]), __float2half_rn(outv[5]));
        __half2 h3 = __halves2half2(__float2half_rn(outv[6]), __float2half_rn(outv[7]));
        uint4 w = { *(uint32_t*)&h0, *(uint32_t*)&h1, *(uint32_t*)&h2, *(uint32_t*)&h3 };
        *(uint4*)&O[base] = w;
    }
}

// ---------------- launch --------------------------------------------------
extern "C" void kernel_launch(void* const* d_in, const int* in_sizes, int n_in,
                              void* d_out, int out_size) {
    const float* x     = (const float*)d_in[0];
    const float* dw1_w = (const float*)d_in[1];
    const float* dw1_b = (const float*)d_in[2];
    const float* pw1_w = (const float*)d_in[3];
    const float* pw1_b = (const float*)d_in[4];
    const float* dw2_w = (const float*)d_in[5];
    const float* dw2_b = (const float*)d_in[6];
    const float* pw2_w = (const float*)d_in[7];
    const float* pw2_b = (const float*)d_in[8];
    const float* wq = (const float*)d_in[9];
    const float* bq = (const float*)d_in[10];
    const float* wk = (const float*)d_in[11];
    const float* bk = (const float*)d_in[12];
    const float* wv = (const float*)d_in[13];
    const float* bv = (const float*)d_in[14];
    const float* wp = (const float*)d_in[15];
    const float* bp = (const float*)d_in[16];
    const float* ff_w = (const float*)d_in[17];
    const float* ff_b = (const float*)d_in[18];
    float* out = (float*)d_out;

    float *pX, *pBqkv;
    __half *pBt, *pQKV, *pWb, *pWb2, *pWqkv;
    cudaGetSymbolAddress((void**)&pX, gX);
    cudaGetSymbolAddress((void**)&pBt, gBt);
    cudaGetSymbolAddress((void**)&pQKV, gQKV);
    cudaGetSymbolAddress((void**)&pWb, gWb);
    cudaGetSymbolAddress((void**)&pWb2, gWb2);
    cudaGetSymbolAddress((void**)&pWqkv, gWqkv);
    cudaGetSymbolAddress((void**)&pBqkv, gBqkv);

    cudaFuncSetAttribute(k_attn, cudaFuncAttributeMaxDynamicSharedMemorySize, ATTN_SMEM_BYTES);
    cudaFuncSetAttribute((k_mma<0, 1, 0, float>), cudaFuncAttributeMaxDynamicSharedMemorySize, MMA_SMEM);
    cudaFuncSetAttribute((k_mma<1, 1, 0, float>), cudaFuncAttributeMaxDynamicSharedMemorySize, MMA_SMEM);
    cudaFuncSetAttribute((k_mma<0, 0, 0, __half>), cudaFuncAttributeMaxDynamicSharedMemorySize, MMA_SMEM);
    cudaFuncSetAttribute((k_mma<1, 2, 0, float>), cudaFuncAttributeMaxDynamicSharedMemorySize, MMA_SMEM);
    cudaFuncSetAttribute((k_mma<1, 0, 1, float>), cudaFuncAttributeMaxDynamicSharedMemorySize, MMA_SMEM);

    dim3 mmaG(4, 512);       // m fast -> B tiles shared across m via L2
    dim3 mmaGqkv(12, 512);

    // 0) zero stat accumulators; input transpose + pos-enc (+batch stats)
    k_zeroacc<<<16, 256>>>();
    k_transpose_in<<<dim3(TT / 32, CC / 32, BB), dim3(32, 8)>>>(x, pX);
    k_bfinal<<<1, 32>>>();

    // 1) conv block 1: X = pw1 @ dwconv1(LN_b(X)) + b   (+batch stats)
    k_dwconv<<<dim3(CC, BB), 256>>>(pX, dw1_w, dw1_b, pBt);
    k_cvtW<<<1024, 256>>>(pw1_w, pWb);
    k_mma<0, 1, 0, float><<<mmaG, 256, MMA_SMEM>>>(pWb, pBt, pw1_b, pX, pX);
    k_bfinal<<<1, 32>>>();

    // 2) conv blocks 2..4 (shared weights)
    k_cvtW<<<1024, 256>>>(pw2_w, pWb2);
    for (int it = 0; it < 3; it++) {
        k_dwconv<<<dim3(CC, BB), 256>>>(pX, dw2_w, dw2_b, pBt);
        k_mma<1, 1, 0, float><<<mmaG, 256, MMA_SMEM>>>(pWb2, pBt, pw2_b, pX, pX);
        k_bfinal<<<1, 32>>>();
    }

    // 3) attention over batch axis (merged QKV GEMM, fp16)
    k_cvtBe<1><<<32768, 256>>>(pX, pBt);
    k_packqkv<<<3072, 256>>>(wq, wk, wv, bq, bk, bv, pWqkv, pBqkv);
    k_mma<0, 0, 0, __half><<<mmaGqkv, 256, MMA_SMEM>>>(pWqkv, pBt, pBqkv, pQKV, (const float*)0);
    k_attn<<<dim3(TT / AT, HH), 256, ATTN_SMEM_BYTES>>>(pQKV, pBt);
    k_cvtW<<<1024, 256>>>(wp, pWb);
    k_mma<1, 2, 0, float><<<mmaG, 256, MMA_SMEM>>>(pWb, pBt, bp, pX, pX);  // +per-t stats
    k_tfinal<<<TT / 256, 256>>>();

    // 4) FF with per-t LN; final GEMM writes output transposed (B,T,F)
    k_cvtBe<2><<<32768, 256>>>(pX, pBt);
    k_cvtW<<<1024, 256>>>(ff_w, pWb);
    k_mma<1, 0, 1, float><<<mmaG, 256, MMA_SMEM>>>(pWb, pBt, ff_b, out, pX);

    (void)in_sizes; (void)n_in; (void)out_size;
}